// round 5
// baseline (speedup 1.0000x reference)
#include <cuda_runtime.h>
#include <math.h>

#define NNODES 512
#define IND    768
#define HIDD   64
#define NHEAD  4
#define HD1    256          // NHEAD*HIDD
#define KCC    192          // IND/4
#define OUTDIM 256
#define NT     256

// ----------------------------------------------------------------------------
// Device scratch (allocation-free)
// ----------------------------------------------------------------------------
__device__ float g_z1[NNODES * HD1];
__device__ float g_h1[NNODES * HD1];
__device__ float g_z2[NNODES * IND];
__device__ float g_h2[NNODES * IND];
__device__ float g_p [NNODES * IND];
__device__ float g_r [NNODES * KCC];
__device__ float g_part[4 * NNODES * IND];        // 6 MB, max split usage
__device__ float g_ssrc[NHEAD * NNODES], g_sdst[NHEAD * NNODES];
__device__ float g_Af[NHEAD * NNODES], g_Cf[NHEAD * NNODES];   // per-src factors
__device__ float g_Bp[NHEAD * NNODES], g_Dp[NHEAD * NNODES];   // per-dst factors * invdenom
__device__ float g_mxc[IND], g_invc[IND];
__device__ float g_rsum[KCC];
__device__ unsigned g_barcnt = 0;
__device__ volatile unsigned g_bargen = 0;

// ----------------------------------------------------------------------------
// Grid-wide software barrier (all CTAs co-resident: grid = #SMs, 1 CTA/SM)
// ----------------------------------------------------------------------------
__device__ __forceinline__ void gridbar() {
    __syncthreads();
    if (threadIdx.x == 0) {
        __threadfence();
        unsigned gen = g_bargen;                    // read BEFORE arriving
        unsigned t = atomicAdd(&g_barcnt, 1u);
        if (t == gridDim.x - 1) {
            g_barcnt = 0;
            __threadfence();
            atomicAdd((unsigned*)&g_bargen, 1u);
        } else {
            while (g_bargen == gen) { __nanosleep(32); }
        }
        __threadfence();
    }
    __syncthreads();
}

// ----------------------------------------------------------------------------
// Phase: SGEMM  Cpart[z][512,Ncols] = A[512,K_ld] @ B[Ncols,K_ld]^T over k-split z
// 64x64 tile, 4x4/thread, smem [k][mn] for LDS.128 fragments.
// ----------------------------------------------------------------------------
__device__ void ph_gemm_abt(const float* __restrict__ A, const float* __restrict__ B,
                            float* __restrict__ C, int Ncols, int K_ld,
                            int klen, int gx, int gy, int nsplit, float* sm)
{
    float (*As)[68] = (float(*)[68])sm;
    float (*Bs)[68] = (float(*)[68])(sm + 1088);
    const int tid = threadIdx.x;
    const int tx = tid & 15, ty = tid >> 4;
    const int r = tid >> 2, kc = (tid & 3) << 2;
    const int njobs = gx * gy * nsplit;

    for (int job = blockIdx.x; job < njobs; job += gridDim.x) {
        const int z = job / (gx * gy);
        const int rem = job % (gx * gy);
        const int by = rem / gx, bx = rem % gx;
        const int m0 = by * 64, n0 = bx * 64, kstart = z * klen;

        float acc[4][4];
#pragma unroll
        for (int i = 0; i < 4; i++)
#pragma unroll
            for (int j = 0; j < 4; j++) acc[i][j] = 0.f;

        __syncthreads();
        for (int k0 = 0; k0 < klen; k0 += 16) {
            const int kg = kstart + k0 + kc;
            float4 av = *(const float4*)&A[(size_t)(m0 + r) * K_ld + kg];
            As[kc + 0][r] = av.x; As[kc + 1][r] = av.y;
            As[kc + 2][r] = av.z; As[kc + 3][r] = av.w;
            float4 bv = *(const float4*)&B[(size_t)(n0 + r) * K_ld + kg];
            Bs[kc + 0][r] = bv.x; Bs[kc + 1][r] = bv.y;
            Bs[kc + 2][r] = bv.z; Bs[kc + 3][r] = bv.w;
            __syncthreads();
#pragma unroll
            for (int kk = 0; kk < 16; kk++) {
                float4 a = *(const float4*)&As[kk][ty * 4];
                float4 b = *(const float4*)&Bs[kk][tx * 4];
                float a4[4] = {a.x, a.y, a.z, a.w};
                float b4[4] = {b.x, b.y, b.z, b.w};
#pragma unroll
                for (int i = 0; i < 4; i++)
#pragma unroll
                    for (int j = 0; j < 4; j++) acc[i][j] += a4[i] * b4[j];
            }
            __syncthreads();
        }
        float* outp = C + (size_t)z * NNODES * Ncols;
#pragma unroll
        for (int i = 0; i < 4; i++)
#pragma unroll
            for (int j = 0; j < 4; j++)
                outp[(size_t)(m0 + ty * 4 + i) * Ncols + n0 + tx * 4 + j] = acc[i][j];
    }
}

// ----------------------------------------------------------------------------
// Phase: aggregation GEMM with on-the-fly alpha:
//   alpha[j][i] = (i!=j) * select(s_i+d_j > 0, Af_i*Bp_j, Cf_i*Dp_j)
//   Cpart[z][j, col] = sum_k alpha[j][k] * Z[k][col]
// ----------------------------------------------------------------------------
__device__ void ph_gemm_agg(const float* __restrict__ Z, float* __restrict__ C,
                            const float* __restrict__ ssrc, const float* __restrict__ sdst,
                            const float* __restrict__ Af, const float* __restrict__ Cf,
                            const float* __restrict__ Bp, const float* __restrict__ Dp,
                            int ldz, int hd, int gx, int gy, int nsplit, int H,
                            int klen, int ldc, float* sm)
{
    float (*As)[68] = (float(*)[68])sm;
    float (*Bs)[68] = (float(*)[68])(sm + 1088);
    float* Ex = sm + 2176;   // dj[64], Bp[64], Dp[64]
    const int tid = threadIdx.x;
    const int tx = tid & 15, ty = tid >> 4;
    const int row16 = tid >> 4, c4 = (tid & 15) << 2;
    const int jobs_per_h = gx * gy * nsplit;
    const int njobs = H * jobs_per_h;

    for (int job = blockIdx.x; job < njobs; job += gridDim.x) {
        const int h = job / jobs_per_h;
        int rem = job % jobs_per_h;
        const int z = rem / (gx * gy); rem %= gx * gy;
        const int by = rem / gx, bx = rem % gx;
        const int m0 = by * 64, ncol0 = h * hd + bx * 64, kstart = z * klen;
        const float* ss = ssrc + h * NNODES;
        const float* af = Af + h * NNODES;
        const float* cf = Cf + h * NNODES;

        __syncthreads();
        for (int t = tid; t < 64; t += NT) {
            int j = m0 + t;
            Ex[t]       = sdst[h * NNODES + j];
            Ex[64 + t]  = Bp[h * NNODES + j];
            Ex[128 + t] = Dp[h * NNODES + j];
        }
        __syncthreads();

        float acc[4][4];
#pragma unroll
        for (int i = 0; i < 4; i++)
#pragma unroll
            for (int j = 0; j < 4; j++) acc[i][j] = 0.f;

        for (int k0 = 0; k0 < klen; k0 += 16) {
            // construct alpha tile into As[k][j]
            for (int t = tid; t < 1024; t += NT) {
                int ii = t >> 6, jj = t & 63;
                int ig = kstart + k0 + ii;
                float x = ss[ig] + Ex[jj];
                float w = (x > 0.f) ? af[ig] * Ex[64 + jj] : cf[ig] * Ex[128 + jj];
                if (ig == m0 + jj) w = 0.f;
                As[ii][jj] = w;
            }
            float4 bv = *(const float4*)&Z[(size_t)(kstart + k0 + row16) * ldz + ncol0 + c4];
            Bs[row16][c4 + 0] = bv.x; Bs[row16][c4 + 1] = bv.y;
            Bs[row16][c4 + 2] = bv.z; Bs[row16][c4 + 3] = bv.w;
            __syncthreads();
#pragma unroll
            for (int kk = 0; kk < 16; kk++) {
                float4 a = *(const float4*)&As[kk][ty * 4];
                float4 b = *(const float4*)&Bs[kk][tx * 4];
                float a4[4] = {a.x, a.y, a.z, a.w};
                float b4[4] = {b.x, b.y, b.z, b.w};
#pragma unroll
                for (int i = 0; i < 4; i++)
#pragma unroll
                    for (int j = 0; j < 4; j++) acc[i][j] += a4[i] * b4[j];
            }
            __syncthreads();
        }
        float* outp = C + (size_t)z * NNODES * ldc;
#pragma unroll
        for (int i = 0; i < 4; i++)
#pragma unroll
            for (int j = 0; j < 4; j++)
                outp[(size_t)(m0 + ty * 4 + i) * ldc + ncol0 + tx * 4 + j] = acc[i][j];
    }
}

// ----------------------------------------------------------------------------
// Phase: combine k-split partials (+ bias, + activation)
// ----------------------------------------------------------------------------
__device__ void ph_combine(float* __restrict__ out, const float* __restrict__ part,
                           int nparts, int total, int ncols,
                           const float* __restrict__ bias, int act)
{
    for (int idx = blockIdx.x * NT + threadIdx.x; idx < total; idx += gridDim.x * NT) {
        float s = 0.f;
        for (int p = 0; p < nparts; p++) s += part[(size_t)p * total + idx];
        if (bias) s += bias[idx % ncols];
        if (act == 1) s = fmaxf(s, 0.f);
        else if (act == 2) s = s > 0.f ? s : expm1f(s);
        out[idx] = s;
    }
}

// ----------------------------------------------------------------------------
// Phase: per-node attention scores (warp per (h,i))
// ----------------------------------------------------------------------------
__device__ void ph_scores(const float* __restrict__ z, int ldz,
                          const float* __restrict__ a, int D,
                          float* __restrict__ ssrc, float* __restrict__ sdst, int H)
{
    const int lane = threadIdx.x & 31;
    const int gw = blockIdx.x * (NT / 32) + (threadIdx.x >> 5);
    const int nw = gridDim.x * (NT / 32);
    for (int w = gw; w < H * NNODES; w += nw) {
        int h = w / NNODES, i = w % NNODES;
        const float* zr = z + (size_t)i * ldz + h * D;
        const float* ar = a + (size_t)h * 2 * D;
        float s1 = 0.f, s2 = 0.f;
        for (int d = lane; d < D; d += 32) {
            float v = zr[d];
            s1 += v * ar[d];
            s2 += v * ar[D + d];
        }
#pragma unroll
        for (int o = 16; o; o >>= 1) {
            s1 += __shfl_xor_sync(0xffffffffu, s1, o);
            s2 += __shfl_xor_sync(0xffffffffu, s2, o);
        }
        if (lane == 0) { ssrc[h * NNODES + i] = s1; sdst[h * NNODES + i] = s2; }
    }
}

// ----------------------------------------------------------------------------
// Phase: separable-softmax stats. Block per (h, 64-j chunk).
//   Ms = max_i s_i, M2 = 2nd max (for j == argmax), per-j:
//   mx_j = lrelu(smax_{i!=j} + d_j);  B_j = e^{Ms+d_j-mx_j};  D_j = e^{0.01(Ms+d_j)-mx_j}
//   denom_j via select-products (no exp); Bp/Dp = B/D * (1/denom)
// ----------------------------------------------------------------------------
__device__ void ph_stats(const float* __restrict__ ssrc, const float* __restrict__ sdst,
                         float* __restrict__ Af, float* __restrict__ Cf,
                         float* __restrict__ Bpg, float* __restrict__ Dpg,
                         int H, float* sm)
{
    float* ss  = sm;          // 512
    float* aa  = sm + 512;    // 512
    float* cc  = sm + 1024;   // 512
    float* rm1 = sm + 1536;   // 256
    float* rm2 = sm + 1792;   // 256
    int*   ri1 = (int*)(sm + 2048);  // 256
    const int tid = threadIdx.x;
    const int cpj = NNODES / 64;     // 8 chunks per head
    const int njobs = H * cpj;

    for (int job = blockIdx.x; job < njobs; job += gridDim.x) {
        const int h = job / cpj, jc = job % cpj;
        __syncthreads();
        for (int i = tid; i < NNODES; i += NT) ss[i] = ssrc[h * NNODES + i];
        __syncthreads();

        // top-2 (+argmax) of src scores
        float m1 = -1e30f, m2 = -1e30f; int i1 = -1;
        for (int i = tid; i < NNODES; i += NT) {
            float v = ss[i];
            if (v > m1) { m2 = m1; m1 = v; i1 = i; }
            else if (v > m2) m2 = v;
        }
        rm1[tid] = m1; rm2[tid] = m2; ri1[tid] = i1;
        __syncthreads();
        if (tid < 32) {
            float a1 = rm1[tid], a2 = rm2[tid]; int ai = ri1[tid];
            for (int t = tid + 32; t < NT; t += 32) {
                float b1 = rm1[t], b2 = rm2[t];
                if (b1 > a1) { a2 = fmaxf(a1, b2); a1 = b1; ai = ri1[t]; }
                else         { a2 = fmaxf(a2, b1); }
            }
            rm1[tid] = a1; rm2[tid] = a2; ri1[tid] = ai;
        }
        __syncthreads();
        if (tid == 0) {
            float a1 = rm1[0], a2 = rm2[0]; int ai = ri1[0];
            for (int t = 1; t < 32; t++) {
                float b1 = rm1[t], b2 = rm2[t];
                if (b1 > a1) { a2 = fmaxf(a1, b2); a1 = b1; ai = ri1[t]; }
                else         { a2 = fmaxf(a2, b1); }
            }
            rm1[0] = a1; rm2[0] = a2; ri1[0] = ai;
        }
        __syncthreads();
        const float Ms = rm1[0], M2 = rm2[0];
        const int iarg = ri1[0];

        for (int i = tid; i < NNODES; i += NT) {
            float d = ss[i] - Ms;
            aa[i] = __expf(d);
            cc[i] = __expf(0.01f * d);
        }
        __syncthreads();
        if (jc == 0) {
            for (int i = tid; i < NNODES; i += NT) {
                Af[h * NNODES + i] = aa[i];
                Cf[h * NNODES + i] = cc[i];
            }
        }

        const int wid = tid >> 5, lane = tid & 31;
        for (int jj = wid; jj < 64; jj += 8) {
            int j = jc * 64 + jj;
            float sd = sdst[h * NNODES + j];
            float smx = (j == iarg) ? M2 : Ms;
            float t0 = smx + sd;
            float mxj = t0 > 0.f ? t0 : 0.01f * t0;
            float Bj = __expf(Ms + sd - mxj);
            float Dj = __expf(0.01f * (Ms + sd) - mxj);
            float ssum = 0.f;
            for (int i = lane; i < NNODES; i += 32) {
                if (i == j) continue;
                float x = ss[i] + sd;
                ssum += (x > 0.f) ? aa[i] * Bj : cc[i] * Dj;
            }
#pragma unroll
            for (int o = 16; o; o >>= 1) ssum += __shfl_xor_sync(0xffffffffu, ssum, o);
            if (lane == 0) {
                float inv = 1.f / ssum;
                Bpg[h * NNODES + j] = Bj * inv;
                Dpg[h * NNODES + j] = Dj * inv;
            }
        }
    }
}

// ----------------------------------------------------------------------------
// Phase: column softmax stats (max, 1/sum) over nodes, coalesced
// ----------------------------------------------------------------------------
__device__ void ph_colstats(const float* __restrict__ h2,
                            float* __restrict__ mxc, float* __restrict__ invc, float* sm)
{
    float* red  = sm;        // 256
    float* red2 = sm + 256;  // 256
    const int tid = threadIdx.x;
    const int fl = tid & 63, rg = tid >> 6;
    for (int job = blockIdx.x; job < IND / 64; job += gridDim.x) {
        const int f = job * 64 + fl;
        __syncthreads();
        float m = -1e30f;
        for (int r0 = rg; r0 < NNODES; r0 += 4) m = fmaxf(m, h2[(size_t)r0 * IND + f]);
        red[rg * 64 + fl] = m;
        __syncthreads();
        if (rg == 0)
            red[fl] = fmaxf(fmaxf(red[fl], red[64 + fl]), fmaxf(red[128 + fl], red[192 + fl]));
        __syncthreads();
        const float mf = red[fl];
        float s = 0.f;
        for (int r0 = rg; r0 < NNODES; r0 += 4) s += __expf(h2[(size_t)r0 * IND + f] - mf);
        red2[rg * 64 + fl] = s;
        __syncthreads();
        if (rg == 0) {
            float t = red2[fl] + red2[64 + fl] + red2[128 + fl] + red2[192 + fl];
            mxc[f] = mf;
            invc[f] = 1.f / t;
        }
    }
}

// ----------------------------------------------------------------------------
// Phase: materialize p = softmax(h2, axis=0) (vectorized)
// ----------------------------------------------------------------------------
__device__ void ph_pmat(const float* __restrict__ h2, const float* __restrict__ mxc,
                        const float* __restrict__ invc, float* __restrict__ p)
{
    const int total4 = NNODES * IND / 4;
    for (int q = blockIdx.x * NT + threadIdx.x; q < total4; q += gridDim.x * NT) {
        int idx = q * 4;
        int c = idx % IND;
        float4 v  = *(const float4*)&h2[idx];
        float4 mx = *(const float4*)&mxc[c];
        float4 iv = *(const float4*)&invc[c];
        float4 o;
        o.x = __expf(v.x - mx.x) * iv.x;
        o.y = __expf(v.y - mx.y) * iv.y;
        o.z = __expf(v.z - mx.z) * iv.z;
        o.w = __expf(v.w - mx.w) * iv.w;
        *(float4*)&p[idx] = o;
    }
}

// ----------------------------------------------------------------------------
// Phase: column sum of r -> rsum
// ----------------------------------------------------------------------------
__device__ void ph_colsum(const float* __restrict__ r, float* __restrict__ rsum, float* sm)
{
    const int tid = threadIdx.x;
    const int cl = tid & 31, rg = tid >> 5;   // 8 row groups
    for (int job = blockIdx.x; job < KCC / 32; job += gridDim.x) {
        const int c = job * 32 + cl;
        __syncthreads();
        float s = 0.f;
        for (int r0 = rg; r0 < NNODES; r0 += 8) s += r[(size_t)r0 * KCC + c];
        sm[rg * 32 + cl] = s;
        __syncthreads();
        if (rg == 0) {
            float t = 0.f;
            for (int g = 0; g < 8; g++) t += sm[g * 32 + cl];
            rsum[c] = t;
        }
    }
}

// ----------------------------------------------------------------------------
// Phase: out[o] = N*fc2_b[o] + dot(rsum, fc2_w[o,:])  (warp per output)
// ----------------------------------------------------------------------------
__device__ void ph_fc2(const float* __restrict__ rsum, const float* __restrict__ w,
                       const float* __restrict__ b, float* __restrict__ out)
{
    const int lane = threadIdx.x & 31;
    const int gw = blockIdx.x * (NT / 32) + (threadIdx.x >> 5);
    const int nw = gridDim.x * (NT / 32);
    for (int o = gw; o < OUTDIM; o += nw) {
        float s = 0.f;
        for (int k = lane; k < KCC; k += 32) s += rsum[k] * w[(size_t)o * KCC + k];
#pragma unroll
        for (int of = 16; of; of >>= 1) s += __shfl_xor_sync(0xffffffffu, s, of);
        if (lane == 0) out[o] = (float)NNODES * b[o] + s;
    }
}

// ----------------------------------------------------------------------------
// The persistent mega-kernel: 17 phases, grid barriers between
// ----------------------------------------------------------------------------
__global__ void __launch_bounds__(NT, 1)
gat_mega(const float* __restrict__ X,  const float* __restrict__ W1,
         const float* __restrict__ a1, const float* __restrict__ W2,
         const float* __restrict__ a2, const float* __restrict__ fc1w,
         const float* __restrict__ fc1b, const float* __restrict__ fc2w,
         const float* __restrict__ fc2b, float* __restrict__ out)
{
    __shared__ float sm[2432];

    // P0: z1 partial = X @ W1^T, K=768 split 8 (256 jobs)
    ph_gemm_abt(X, W1, g_part, HD1, IND, 96, HD1 / 64, NNODES / 64, 8, sm);
    gridbar();
    // P1: combine -> z1
    ph_combine(g_z1, g_part, 8, NNODES * HD1, HD1, nullptr, 0);
    gridbar();
    // P2: layer1 scores
    ph_scores(g_z1, HD1, a1, HIDD, g_ssrc, g_sdst, NHEAD);
    gridbar();
    // P3: layer1 separable-softmax stats
    ph_stats(g_ssrc, g_sdst, g_Af, g_Cf, g_Bp, g_Dp, NHEAD, sm);
    gridbar();
    // P4: agg1 = alpha1 @ z1 (on-the-fly alpha), split 8 (256 jobs)
    ph_gemm_agg(g_z1, g_part, g_ssrc, g_sdst, g_Af, g_Cf, g_Bp, g_Dp,
                HD1, HIDD, 1, NNODES / 64, 8, NHEAD, 64, HD1, sm);
    gridbar();
    // P5: combine + ELU -> h1
    ph_combine(g_h1, g_part, 8, NNODES * HD1, HD1, nullptr, 2);
    gridbar();
    // P6: z2 = h1 @ W2^T, K=256 (96 jobs, direct write)
    ph_gemm_abt(g_h1, W2, g_z2, IND, HD1, 256, IND / 64, NNODES / 64, 1, sm);
    gridbar();
    // P7: layer2 scores
    ph_scores(g_z2, IND, a2, IND, g_ssrc, g_sdst, 1);
    gridbar();
    // P8: layer2 stats
    ph_stats(g_ssrc, g_sdst, g_Af, g_Cf, g_Bp, g_Dp, 1, sm);
    gridbar();
    // P9: agg2 = alpha2 @ z2 (on-the-fly alpha), split 4 (384 jobs)
    ph_gemm_agg(g_z2, g_part, g_ssrc, g_sdst, g_Af, g_Cf, g_Bp, g_Dp,
                IND, 0, IND / 64, NNODES / 64, 4, 1, 128, IND, sm);
    gridbar();
    // P10: combine -> h2
    ph_combine(g_h2, g_part, 4, NNODES * IND, IND, nullptr, 0);
    gridbar();
    // P11: column softmax stats
    ph_colstats(g_h2, g_mxc, g_invc, sm);
    gridbar();
    // P12: materialize p
    ph_pmat(g_h2, g_mxc, g_invc, g_p);
    gridbar();
    // P13: fc1 partial = p @ fc1_w^T, K=768 split 8 (192 jobs)
    ph_gemm_abt(g_p, fc1w, g_part, KCC, IND, 96, KCC / 64, NNODES / 64, 8, sm);
    gridbar();
    // P14: combine + bias + relu -> r
    ph_combine(g_r, g_part, 8, NNODES * KCC, KCC, fc1b, 1);
    gridbar();
    // P15: column sum -> rsum
    ph_colsum(g_r, g_rsum, sm);
    gridbar();
    // P16: fc2 -> out
    ph_fc2(g_rsum, fc2w, fc2b, out);
}

// ----------------------------------------------------------------------------
// Launch: one persistent kernel, grid = #SMs (all CTAs co-resident)
// ----------------------------------------------------------------------------
extern "C" void kernel_launch(void* const* d_in, const int* in_sizes, int n_in,
                              void* d_out, int out_size)
{
    const float* X     = (const float*)d_in[0];
    const float* W1    = (const float*)d_in[1];
    const float* a1    = (const float*)d_in[2];
    const float* W2    = (const float*)d_in[3];
    const float* a2    = (const float*)d_in[4];
    const float* fc1_w = (const float*)d_in[5];
    const float* fc1_b = (const float*)d_in[6];
    const float* fc2_w = (const float*)d_in[7];
    const float* fc2_b = (const float*)d_in[8];

    int sms = 148;
    cudaDeviceGetAttribute(&sms, cudaDevAttrMultiProcessorCount, 0);

    gat_mega<<<sms, NT>>>(X, W1, a1, W2, a2, fc1_w, fc1_b, fc2_w, fc2_b, (float*)d_out);
}

// round 6
// speedup vs baseline: 1.1031x; 1.1031x over previous
#include <cuda_runtime.h>
#include <math.h>

#define NNODES 512
#define IND    768
#define HIDD   64
#define NHEAD  4
#define HD1    256          // NHEAD*HIDD
#define KCC    192          // IND/4
#define OUTDIM 256
#define NT     768          // threads per CTA
#define NG     3            // warpgroups per CTA
#define GSZ    256          // threads per warpgroup
#define SMG    2432         // smem floats per warpgroup

// ----------------------------------------------------------------------------
// Device scratch
// ----------------------------------------------------------------------------
__device__ float g_z1[NNODES * HD1];
__device__ float g_h1[NNODES * HD1];
__device__ float g_z2[NNODES * IND];
__device__ float g_h2[NNODES * IND];
__device__ float g_p [NNODES * IND];
__device__ float g_r [NNODES * KCC];
__device__ float g_part[4 * NNODES * IND];        // 6 MB partial-K buffer
__device__ float g_ssrc[NHEAD * NNODES], g_sdst[NHEAD * NNODES];
__device__ float g_Af[NHEAD * NNODES], g_Cf[NHEAD * NNODES];
__device__ float g_Bp[NHEAD * NNODES], g_Dp[NHEAD * NNODES];
__device__ float g_mxc[IND], g_invc[IND];
__device__ float g_rsum[KCC];
__device__ unsigned g_barcnt = 0;
__device__ volatile unsigned g_bargen = 0;

// ----------------------------------------------------------------------------
// Warpgroup barrier (named, 256 threads) + grid barrier
// ----------------------------------------------------------------------------
__device__ __forceinline__ void wgsync(int wg) {
    asm volatile("bar.sync %0, %1;" :: "r"(wg + 1), "n"(GSZ) : "memory");
}

__device__ __forceinline__ void gridbar() {
    __syncthreads();
    if (threadIdx.x == 0) {
        __threadfence();
        unsigned gen = g_bargen;
        unsigned t = atomicAdd(&g_barcnt, 1u);
        if (t == gridDim.x - 1) {
            g_barcnt = 0;
            __threadfence();
            atomicAdd((unsigned*)&g_bargen, 1u);
        } else {
            while (g_bargen == gen) { __nanosleep(32); }
        }
        __threadfence();
    }
    __syncthreads();
}

// ----------------------------------------------------------------------------
// GEMM phase: Cpart[z][512,Ncols] = A[512,K_ld] @ B[Ncols,K_ld]^T, k-split.
// One 64x64 tile per warpgroup job; 4x4/thread; smem [k][mn].
// ----------------------------------------------------------------------------
__device__ void ph_gemm_abt(const float* __restrict__ A, const float* __restrict__ B,
                            float* __restrict__ C, int Ncols, int K_ld,
                            int klen, int gx, int gy, int nsplit,
                            int ltid, int wg, int grp, int ngrp, float* gsm)
{
    float (*As)[68] = (float(*)[68])gsm;
    float (*Bs)[68] = (float(*)[68])(gsm + 1088);
    const int tx = ltid & 15, ty = ltid >> 4;
    const int r = ltid >> 2, kc = (ltid & 3) << 2;
    const int njobs = gx * gy * nsplit;

    for (int job = grp; job < njobs; job += ngrp) {
        const int z = job / (gx * gy);
        const int rem = job % (gx * gy);
        const int by = rem / gx, bx = rem % gx;
        const int m0 = by * 64, n0 = bx * 64, kstart = z * klen;

        float acc[4][4];
#pragma unroll
        for (int i = 0; i < 4; i++)
#pragma unroll
            for (int j = 0; j < 4; j++) acc[i][j] = 0.f;

        wgsync(wg);
        for (int k0 = 0; k0 < klen; k0 += 16) {
            const int kg = kstart + k0 + kc;
            float4 av = *(const float4*)&A[(size_t)(m0 + r) * K_ld + kg];
            As[kc + 0][r] = av.x; As[kc + 1][r] = av.y;
            As[kc + 2][r] = av.z; As[kc + 3][r] = av.w;
            float4 bv = *(const float4*)&B[(size_t)(n0 + r) * K_ld + kg];
            Bs[kc + 0][r] = bv.x; Bs[kc + 1][r] = bv.y;
            Bs[kc + 2][r] = bv.z; Bs[kc + 3][r] = bv.w;
            wgsync(wg);
#pragma unroll
            for (int kk = 0; kk < 16; kk++) {
                float4 a = *(const float4*)&As[kk][ty * 4];
                float4 b = *(const float4*)&Bs[kk][tx * 4];
                float a4[4] = {a.x, a.y, a.z, a.w};
                float b4[4] = {b.x, b.y, b.z, b.w};
#pragma unroll
                for (int i = 0; i < 4; i++)
#pragma unroll
                    for (int j = 0; j < 4; j++) acc[i][j] += a4[i] * b4[j];
            }
            wgsync(wg);
        }
        float* outp = C + (size_t)z * NNODES * Ncols;
#pragma unroll
        for (int i = 0; i < 4; i++)
#pragma unroll
            for (int j = 0; j < 4; j++)
                outp[(size_t)(m0 + ty * 4 + i) * Ncols + n0 + tx * 4 + j] = acc[i][j];
    }
}

// ----------------------------------------------------------------------------
// Aggregation GEMM with on-the-fly alpha (separable softmax factors)
// ----------------------------------------------------------------------------
__device__ void ph_gemm_agg(const float* __restrict__ Z, float* __restrict__ C,
                            const float* __restrict__ ssrc, const float* __restrict__ sdst,
                            const float* __restrict__ Af, const float* __restrict__ Cf,
                            const float* __restrict__ Bp, const float* __restrict__ Dp,
                            int ldz, int hd, int gx, int gy, int nsplit, int H,
                            int klen, int ldc,
                            int ltid, int wg, int grp, int ngrp, float* gsm)
{
    float (*As)[68] = (float(*)[68])gsm;
    float (*Bs)[68] = (float(*)[68])(gsm + 1088);
    float* Ex = gsm + 2176;   // dj[64], Bp[64], Dp[64]
    const int tx = ltid & 15, ty = ltid >> 4;
    const int row16 = ltid >> 4, c4 = (ltid & 15) << 2;
    const int jobs_per_h = gx * gy * nsplit;
    const int njobs = H * jobs_per_h;

    for (int job = grp; job < njobs; job += ngrp) {
        const int h = job / jobs_per_h;
        int rem = job % jobs_per_h;
        const int z = rem / (gx * gy); rem %= gx * gy;
        const int by = rem / gx, bx = rem % gx;
        const int m0 = by * 64, ncol0 = h * hd + bx * 64, kstart = z * klen;
        const float* ss = ssrc + h * NNODES;
        const float* af = Af + h * NNODES;
        const float* cf = Cf + h * NNODES;

        wgsync(wg);
        if (ltid < 64) {
            int j = m0 + ltid;
            Ex[ltid]       = sdst[h * NNODES + j];
            Ex[64 + ltid]  = Bp[h * NNODES + j];
            Ex[128 + ltid] = Dp[h * NNODES + j];
        }
        wgsync(wg);

        float acc[4][4];
#pragma unroll
        for (int i = 0; i < 4; i++)
#pragma unroll
            for (int j = 0; j < 4; j++) acc[i][j] = 0.f;

        for (int k0 = 0; k0 < klen; k0 += 16) {
            for (int t = ltid; t < 1024; t += GSZ) {
                int ii = t >> 6, jj = t & 63;
                int ig = kstart + k0 + ii;
                float x = ss[ig] + Ex[jj];
                float w = (x > 0.f) ? af[ig] * Ex[64 + jj] : cf[ig] * Ex[128 + jj];
                if (ig == m0 + jj) w = 0.f;
                As[ii][jj] = w;
            }
            float4 bv = *(const float4*)&Z[(size_t)(kstart + k0 + row16) * ldz + ncol0 + c4];
            Bs[row16][c4 + 0] = bv.x; Bs[row16][c4 + 1] = bv.y;
            Bs[row16][c4 + 2] = bv.z; Bs[row16][c4 + 3] = bv.w;
            wgsync(wg);
#pragma unroll
            for (int kk = 0; kk < 16; kk++) {
                float4 a = *(const float4*)&As[kk][ty * 4];
                float4 b = *(const float4*)&Bs[kk][tx * 4];
                float a4[4] = {a.x, a.y, a.z, a.w};
                float b4[4] = {b.x, b.y, b.z, b.w};
#pragma unroll
                for (int i = 0; i < 4; i++)
#pragma unroll
                    for (int j = 0; j < 4; j++) acc[i][j] += a4[i] * b4[j];
            }
            wgsync(wg);
        }
        float* outp = C + (size_t)z * NNODES * ldc;
#pragma unroll
        for (int i = 0; i < 4; i++)
#pragma unroll
            for (int j = 0; j < 4; j++)
                outp[(size_t)(m0 + ty * 4 + i) * ldc + ncol0 + tx * 4 + j] = acc[i][j];
    }
}

// ----------------------------------------------------------------------------
// Combine k-split partials (+bias, +activation); elementwise over all threads
// ----------------------------------------------------------------------------
__device__ void ph_combine(float* __restrict__ out, const float* __restrict__ part,
                           int nparts, int total, int ncols,
                           const float* __restrict__ bias, int act)
{
    for (int idx = blockIdx.x * NT + threadIdx.x; idx < total; idx += gridDim.x * NT) {
        float s = 0.f;
        for (int p = 0; p < nparts; p++) s += part[(size_t)p * total + idx];
        if (bias) s += bias[idx % ncols];
        if (act == 1) s = fmaxf(s, 0.f);
        else if (act == 2) s = s > 0.f ? s : expm1f(s);
        out[idx] = s;
    }
}

// ----------------------------------------------------------------------------
// Attention scores: warp per (h, i)
// ----------------------------------------------------------------------------
__device__ void ph_scores(const float* __restrict__ z, int ldz,
                          const float* __restrict__ a, int D,
                          float* __restrict__ ssrc, float* __restrict__ sdst, int H)
{
    const int lane = threadIdx.x & 31;
    const int gw = blockIdx.x * (NT / 32) + (threadIdx.x >> 5);
    const int nw = gridDim.x * (NT / 32);
    for (int w = gw; w < H * NNODES; w += nw) {
        int h = w / NNODES, i = w % NNODES;
        const float* zr = z + (size_t)i * ldz + h * D;
        const float* ar = a + (size_t)h * 2 * D;
        float s1 = 0.f, s2 = 0.f;
        for (int d = lane; d < D; d += 32) {
            float v = zr[d];
            s1 += v * ar[d];
            s2 += v * ar[D + d];
        }
#pragma unroll
        for (int o = 16; o; o >>= 1) {
            s1 += __shfl_xor_sync(0xffffffffu, s1, o);
            s2 += __shfl_xor_sync(0xffffffffu, s2, o);
        }
        if (lane == 0) { ssrc[h * NNODES + i] = s1; sdst[h * NNODES + i] = s2; }
    }
}

// ----------------------------------------------------------------------------
// Separable-softmax stats: warpgroup per (h, 64-j chunk)
// ----------------------------------------------------------------------------
__device__ void ph_stats(const float* __restrict__ ssrc, const float* __restrict__ sdst,
                         float* __restrict__ Af, float* __restrict__ Cf,
                         float* __restrict__ Bpg, float* __restrict__ Dpg,
                         int H, int ltid, int wg, int grp, int ngrp, float* gsm)
{
    float* ss  = gsm;
    float* aa  = gsm + 512;
    float* cc  = gsm + 1024;
    float* rm1 = gsm + 1536;
    float* rm2 = gsm + 1792;
    int*   ri1 = (int*)(gsm + 2048);
    const int cpj = NNODES / 64;
    const int njobs = H * cpj;

    for (int job = grp; job < njobs; job += ngrp) {
        const int h = job / cpj, jc = job % cpj;
        wgsync(wg);
        for (int i = ltid; i < NNODES; i += GSZ) ss[i] = ssrc[h * NNODES + i];
        wgsync(wg);

        float m1 = -1e30f, m2 = -1e30f; int i1 = -1;
        for (int i = ltid; i < NNODES; i += GSZ) {
            float v = ss[i];
            if (v > m1) { m2 = m1; m1 = v; i1 = i; }
            else if (v > m2) m2 = v;
        }
        rm1[ltid] = m1; rm2[ltid] = m2; ri1[ltid] = i1;
        wgsync(wg);
        if (ltid < 32) {
            float a1 = rm1[ltid], a2 = rm2[ltid]; int ai = ri1[ltid];
            for (int t = ltid + 32; t < GSZ; t += 32) {
                float b1 = rm1[t], b2 = rm2[t];
                if (b1 > a1) { a2 = fmaxf(a1, b2); a1 = b1; ai = ri1[t]; }
                else         { a2 = fmaxf(a2, b1); }
            }
            rm1[ltid] = a1; rm2[ltid] = a2; ri1[ltid] = ai;
        }
        wgsync(wg);
        if (ltid == 0) {
            float a1 = rm1[0], a2 = rm2[0]; int ai = ri1[0];
            for (int t = 1; t < 32; t++) {
                float b1 = rm1[t], b2 = rm2[t];
                if (b1 > a1) { a2 = fmaxf(a1, b2); a1 = b1; ai = ri1[t]; }
                else         { a2 = fmaxf(a2, b1); }
            }
            rm1[0] = a1; rm2[0] = a2; ri1[0] = ai;
        }
        wgsync(wg);
        const float Ms = rm1[0], M2 = rm2[0];
        const int iarg = ri1[0];

        for (int i = ltid; i < NNODES; i += GSZ) {
            float d = ss[i] - Ms;
            aa[i] = __expf(d);
            cc[i] = __expf(0.01f * d);
        }
        wgsync(wg);
        if (jc == 0) {
            for (int i = ltid; i < NNODES; i += GSZ) {
                Af[h * NNODES + i] = aa[i];
                Cf[h * NNODES + i] = cc[i];
            }
        }

        const int wid = ltid >> 5, lane = ltid & 31;
        for (int jj = wid; jj < 64; jj += 8) {
            int j = jc * 64 + jj;
            float sd = sdst[h * NNODES + j];
            float smx = (j == iarg) ? M2 : Ms;
            float t0 = smx + sd;
            float mxj = t0 > 0.f ? t0 : 0.01f * t0;
            float Bj = __expf(Ms + sd - mxj);
            float Dj = __expf(0.01f * (Ms + sd) - mxj);
            float ssum = 0.f;
            for (int i = lane; i < NNODES; i += 32) {
                if (i == j) continue;
                float x = ss[i] + sd;
                ssum += (x > 0.f) ? aa[i] * Bj : cc[i] * Dj;
            }
#pragma unroll
            for (int o = 16; o; o >>= 1) ssum += __shfl_xor_sync(0xffffffffu, ssum, o);
            if (lane == 0) {
                float inv = 1.f / ssum;
                Bpg[h * NNODES + j] = Bj * inv;
                Dpg[h * NNODES + j] = Dj * inv;
            }
        }
    }
}

// ----------------------------------------------------------------------------
// Column softmax stats: warpgroup per 64-feature chunk
// ----------------------------------------------------------------------------
__device__ void ph_colstats(const float* __restrict__ h2,
                            float* __restrict__ mxc, float* __restrict__ invc,
                            int ltid, int wg, int grp, int ngrp, float* gsm)
{
    float* red  = gsm;
    float* red2 = gsm + 256;
    const int fl = ltid & 63, rg = ltid >> 6;
    for (int job = grp; job < IND / 64; job += ngrp) {
        const int f = job * 64 + fl;
        wgsync(wg);
        float m = -1e30f;
        for (int r0 = rg; r0 < NNODES; r0 += 4) m = fmaxf(m, h2[(size_t)r0 * IND + f]);
        red[rg * 64 + fl] = m;
        wgsync(wg);
        if (rg == 0)
            red[fl] = fmaxf(fmaxf(red[fl], red[64 + fl]), fmaxf(red[128 + fl], red[192 + fl]));
        wgsync(wg);
        const float mf = red[fl];
        float s = 0.f;
        for (int r0 = rg; r0 < NNODES; r0 += 4) s += __expf(h2[(size_t)r0 * IND + f] - mf);
        red2[rg * 64 + fl] = s;
        wgsync(wg);
        if (rg == 0) {
            float t = red2[fl] + red2[64 + fl] + red2[128 + fl] + red2[192 + fl];
            mxc[f] = mf;
            invc[f] = 1.f / t;
        }
    }
}

// ----------------------------------------------------------------------------
// Materialize p = softmax(h2, axis=0)
// ----------------------------------------------------------------------------
__device__ void ph_pmat(const float* __restrict__ h2, const float* __restrict__ mxc,
                        const float* __restrict__ invc, float* __restrict__ p)
{
    const int total4 = NNODES * IND / 4;
    for (int q = blockIdx.x * NT + threadIdx.x; q < total4; q += gridDim.x * NT) {
        int idx = q * 4;
        int c = idx % IND;
        float4 v  = *(const float4*)&h2[idx];
        float4 mx = *(const float4*)&mxc[c];
        float4 iv = *(const float4*)&invc[c];
        float4 o;
        o.x = __expf(v.x - mx.x) * iv.x;
        o.y = __expf(v.y - mx.y) * iv.y;
        o.z = __expf(v.z - mx.z) * iv.z;
        o.w = __expf(v.w - mx.w) * iv.w;
        *(float4*)&p[idx] = o;
    }
}

// ----------------------------------------------------------------------------
// Column sum of r -> rsum: warpgroup per 32-col chunk
// ----------------------------------------------------------------------------
__device__ void ph_colsum(const float* __restrict__ r, float* __restrict__ rsum,
                          int ltid, int wg, int grp, int ngrp, float* gsm)
{
    const int cl = ltid & 31, rg = ltid >> 5;
    for (int job = grp; job < KCC / 32; job += ngrp) {
        const int c = job * 32 + cl;
        wgsync(wg);
        float s = 0.f;
        for (int r0 = rg; r0 < NNODES; r0 += 8) s += r[(size_t)r0 * KCC + c];
        gsm[rg * 32 + cl] = s;
        wgsync(wg);
        if (rg == 0) {
            float t = 0.f;
            for (int g = 0; g < 8; g++) t += gsm[g * 32 + cl];
            rsum[c] = t;
        }
    }
}

// ----------------------------------------------------------------------------
// fc2: warp per output
// ----------------------------------------------------------------------------
__device__ void ph_fc2(const float* __restrict__ rsum, const float* __restrict__ w,
                       const float* __restrict__ b, float* __restrict__ out)
{
    const int lane = threadIdx.x & 31;
    const int gw = blockIdx.x * (NT / 32) + (threadIdx.x >> 5);
    const int nw = gridDim.x * (NT / 32);
    for (int o = gw; o < OUTDIM; o += nw) {
        float s = 0.f;
        for (int k = lane; k < KCC; k += 32) s += rsum[k] * w[(size_t)o * KCC + k];
#pragma unroll
        for (int of = 16; of; of >>= 1) s += __shfl_xor_sync(0xffffffffu, s, of);
        if (lane == 0) out[o] = (float)NNODES * b[o] + s;
    }
}

// ----------------------------------------------------------------------------
// Persistent mega-kernel: 3 warpgroups/CTA, 1 CTA/SM
// ----------------------------------------------------------------------------
__global__ void __launch_bounds__(NT, 1)
gat_mega(const float* __restrict__ X,  const float* __restrict__ W1,
         const float* __restrict__ a1, const float* __restrict__ W2,
         const float* __restrict__ a2, const float* __restrict__ fc1w,
         const float* __restrict__ fc1b, const float* __restrict__ fc2w,
         const float* __restrict__ fc2b, float* __restrict__ out)
{
    __shared__ float sm[NG * SMG];
    const int wg = threadIdx.x >> 8;
    const int ltid = threadIdx.x & 255;
    float* gsm = sm + wg * SMG;
    const int grp = blockIdx.x * NG + wg;
    const int ngrp = gridDim.x * NG;

    // P0: z1 partials = X @ W1^T, K=768 split 8 (256 jobs)
    ph_gemm_abt(X, W1, g_part, HD1, IND, 96, HD1 / 64, NNODES / 64, 8,
                ltid, wg, grp, ngrp, gsm);
    gridbar();
    // P1: combine -> z1
    ph_combine(g_z1, g_part, 8, NNODES * HD1, HD1, nullptr, 0);
    gridbar();
    // P2: layer1 scores
    ph_scores(g_z1, HD1, a1, HIDD, g_ssrc, g_sdst, NHEAD);
    gridbar();
    // P3: layer1 stats
    ph_stats(g_ssrc, g_sdst, g_Af, g_Cf, g_Bp, g_Dp, NHEAD, ltid, wg, grp, ngrp, gsm);
    gridbar();
    // P4: agg1 partials (256 jobs)
    ph_gemm_agg(g_z1, g_part, g_ssrc, g_sdst, g_Af, g_Cf, g_Bp, g_Dp,
                HD1, HIDD, 1, NNODES / 64, 8, NHEAD, 64, HD1,
                ltid, wg, grp, ngrp, gsm);
    gridbar();
    // P5: combine + ELU -> h1
    ph_combine(g_h1, g_part, 8, NNODES * HD1, HD1, nullptr, 2);
    gridbar();
    // P6: z2 partials = h1 @ W2^T, K=256 split 4 (384 jobs)
    ph_gemm_abt(g_h1, W2, g_part, IND, HD1, 64, IND / 64, NNODES / 64, 4,
                ltid, wg, grp, ngrp, gsm);
    gridbar();
    // P6b: combine -> z2
    ph_combine(g_z2, g_part, 4, NNODES * IND, IND, nullptr, 0);
    gridbar();
    // P7: layer2 scores
    ph_scores(g_z2, IND, a2, IND, g_ssrc, g_sdst, 1);
    gridbar();
    // P8: layer2 stats
    ph_stats(g_ssrc, g_sdst, g_Af, g_Cf, g_Bp, g_Dp, 1, ltid, wg, grp, ngrp, gsm);
    gridbar();
    // P9: agg2 partials, split 4 (384 jobs)
    ph_gemm_agg(g_z2, g_part, g_ssrc, g_sdst, g_Af, g_Cf, g_Bp, g_Dp,
                IND, 0, IND / 64, NNODES / 64, 4, 1, 128, IND,
                ltid, wg, grp, ngrp, gsm);
    gridbar();
    // P10: combine -> h2
    ph_combine(g_h2, g_part, 4, NNODES * IND, IND, nullptr, 0);
    gridbar();
    // P11: column softmax stats
    ph_colstats(g_h2, g_mxc, g_invc, ltid, wg, grp, ngrp, gsm);
    gridbar();
    // P12: p = softmax(h2, axis=0)
    ph_pmat(g_h2, g_mxc, g_invc, g_p);
    gridbar();
    // P13: fc1 partials = p @ fc1_w^T, K=768 split 16 (384 jobs)
    ph_gemm_abt(g_p, fc1w, g_part, KCC, IND, 48, KCC / 64, NNODES / 64, 16,
                ltid, wg, grp, ngrp, gsm);
    gridbar();
    // P14: combine + bias + relu -> r
    ph_combine(g_r, g_part, 16, NNODES * KCC, KCC, fc1b, 1);
    gridbar();
    // P15: column sum -> rsum
    ph_colsum(g_r, g_rsum, ltid, wg, grp, ngrp, gsm);
    gridbar();
    // P16: fc2 -> out
    ph_fc2(g_rsum, fc2w, fc2b, out);
}

// ----------------------------------------------------------------------------
// Launch
// ----------------------------------------------------------------------------
extern "C" void kernel_launch(void* const* d_in, const int* in_sizes, int n_in,
                              void* d_out, int out_size)
{
    const float* X     = (const float*)d_in[0];
    const float* W1    = (const float*)d_in[1];
    const float* a1    = (const float*)d_in[2];
    const float* W2    = (const float*)d_in[3];
    const float* a2    = (const float*)d_in[4];
    const float* fc1_w = (const float*)d_in[5];
    const float* fc1_b = (const float*)d_in[6];
    const float* fc2_w = (const float*)d_in[7];
    const float* fc2_b = (const float*)d_in[8];

    int sms = 148;
    cudaDeviceGetAttribute(&sms, cudaDevAttrMultiProcessorCount, 0);

    gat_mega<<<sms, NT>>>(X, W1, a1, W2, a2, fc1_w, fc1_b, fc2_w, fc2_b, (float*)d_out);
}

// round 7
// speedup vs baseline: 1.2671x; 1.1486x over previous
#include <cuda_runtime.h>
#include <math.h>

#define NNODES 512
#define IND    768
#define HIDD   64
#define NHEAD  4
#define HD1    256
#define KCC    192
#define OUTDIM 256
#define NT     768          // threads per CTA
#define NG     3            // warpgroups per CTA
#define GSZ    256
#define SMG    3584         // smem floats per warpgroup

// ----------------------------------------------------------------------------
// Device scratch
// ----------------------------------------------------------------------------
__device__ float g_z1[NNODES * HD1];
__device__ float g_h1[NNODES * HD1];
__device__ float g_z2[NNODES * IND];
__device__ float g_h2[NNODES * IND];
__device__ float g_p [NNODES * IND];
__device__ float g_r [NNODES * KCC];
__device__ float g_part[4 * NNODES * IND];        // 6 MB partial-K buffer
__device__ float g_ssrc[NHEAD * NNODES], g_sdst[NHEAD * NNODES];
__device__ float g_Af[NHEAD * NNODES], g_Cf[NHEAD * NNODES];
__device__ float g_Bp[NHEAD * NNODES], g_Dp[NHEAD * NNODES];
__device__ float g_mxc[IND], g_invc[IND];
__device__ float g_rsum[KCC];
__device__ unsigned g_barcnt = 0;
__device__ volatile unsigned g_bargen = 0;

// ----------------------------------------------------------------------------
// Barriers + cp.async helpers
// ----------------------------------------------------------------------------
__device__ __forceinline__ void wgsync(int wg) {
    asm volatile("bar.sync %0, %1;" :: "r"(wg + 1), "n"(GSZ) : "memory");
}

__device__ __forceinline__ void gridbar() {
    __syncthreads();
    if (threadIdx.x == 0) {
        __threadfence();
        unsigned gen = g_bargen;
        unsigned t = atomicAdd(&g_barcnt, 1u);
        if (t == gridDim.x - 1) {
            g_barcnt = 0;
            __threadfence();
            atomicAdd((unsigned*)&g_bargen, 1u);
        } else {
            while (g_bargen == gen) { __nanosleep(32); }
        }
        __threadfence();
    }
    __syncthreads();
}

__device__ __forceinline__ unsigned su32(const void* p) {
    return (unsigned)__cvta_generic_to_shared(p);
}
__device__ __forceinline__ void cpa16(unsigned d, const void* s) {
    asm volatile("cp.async.cg.shared.global [%0], [%1], 16;" :: "r"(d), "l"(s));
}
__device__ __forceinline__ void cpcommit() { asm volatile("cp.async.commit_group;"); }
__device__ __forceinline__ void cpwait0()  { asm volatile("cp.async.wait_group 0;"); }
__device__ __forceinline__ void cpwait1()  { asm volatile("cp.async.wait_group 1;"); }

// ----------------------------------------------------------------------------
// Pipelined SGEMM (dot-product layout): Cpart[z] = A[512,K]@B[N,K]^T, chunk=8
// smem: As[2][64][12], Bs[2][64][12] (row stride 12 floats = 3 f4, odd)
// thread t<128 streams A rows, t>=128 streams B rows; frag m = ty+16i, n = tx+16j
// ----------------------------------------------------------------------------
__device__ void ph_gemm_abt(const float* __restrict__ A, const float* __restrict__ B,
                            float* __restrict__ C, int Ncols, int K_ld, int klen,
                            int gx, int gy, int nsplit,
                            int ltid, int wg, int grp, int ngrp, float* gsm)
{
    float* As = gsm;            // 2*768
    float* Bs = gsm + 1536;     // 2*768
    const int tx = ltid & 15, ty = ltid >> 4;
    const int isB  = ltid >> 7;
    const int lrow = (ltid & 127) >> 1;
    const int lf4  = ltid & 1;
    const int njobs = gx * gy * nsplit;
    const int nch = klen >> 3;

    for (int job = grp; job < njobs; job += ngrp) {
        const int z = job / (gx * gy);
        const int rem = job % (gx * gy);
        const int by = rem / gx, bx = rem % gx;
        const int m0 = by * 64, n0 = bx * 64, kstart = z * klen;

        const float* src0 = isB ? (B + (size_t)(n0 + lrow) * K_ld + kstart + lf4 * 4)
                                : (A + (size_t)(m0 + lrow) * K_ld + kstart + lf4 * 4);
        const unsigned dst0 = isB ? su32(&Bs[lrow * 12 + lf4 * 4])
                                  : su32(&As[lrow * 12 + lf4 * 4]);

        float acc[4][4];
#pragma unroll
        for (int i = 0; i < 4; i++)
#pragma unroll
            for (int j = 0; j < 4; j++) acc[i][j] = 0.f;

        wgsync(wg);                       // smem reuse guard across jobs
        cpa16(dst0, src0);                // chunk 0 -> buf 0
        cpcommit();

        for (int c = 0; c < nch; c++) {
            const int cb = c & 1;
            if (c + 1 < nch) {
                cpa16(dst0 + (cb ^ 1) * 3072, src0 + (c + 1) * 8);
                cpcommit();
                cpwait1();
            } else {
                cpwait0();
            }
            wgsync(wg);

            const float* Ab = As + cb * 768;
            const float* Bb = Bs + cb * 768;
#pragma unroll
            for (int q = 0; q < 2; q++) {
                float4 af[4], bf[4];
#pragma unroll
                for (int i = 0; i < 4; i++)
                    af[i] = *(const float4*)&Ab[(ty + 16 * i) * 12 + q * 4];
#pragma unroll
                for (int j = 0; j < 4; j++)
                    bf[j] = *(const float4*)&Bb[(tx + 16 * j) * 12 + q * 4];
#pragma unroll
                for (int i = 0; i < 4; i++)
#pragma unroll
                    for (int j = 0; j < 4; j++) {
                        acc[i][j] += af[i].x * bf[j].x;
                        acc[i][j] += af[i].y * bf[j].y;
                        acc[i][j] += af[i].z * bf[j].z;
                        acc[i][j] += af[i].w * bf[j].w;
                    }
            }
            wgsync(wg);
        }

        float* outp = C + (size_t)z * NNODES * Ncols;
#pragma unroll
        for (int i = 0; i < 4; i++)
#pragma unroll
            for (int j = 0; j < 4; j++)
                outp[(size_t)(m0 + ty + 16 * i) * Ncols + n0 + tx + 16 * j] = acc[i][j];
    }
}

// ----------------------------------------------------------------------------
// Pipelined aggregation GEMM (outer-product layout), chunk=16:
//   alpha[j][i] = (i!=j)*sel(ss[i]+d[j]>0, Af[i]*Bp[j], Cf[i]*Dp[j]) built in smem,
//   Z streamed via cp.async.  out[j,col] = sum_i alpha[j][i] Z[i][col]
// smem: Asb[16][68], Zs[2][16][68], Ex[192]
// ----------------------------------------------------------------------------
__device__ void ph_gemm_agg(const float* __restrict__ Z, float* __restrict__ C,
                            const float* __restrict__ ssrc, const float* __restrict__ sdst,
                            const float* __restrict__ Af, const float* __restrict__ Cf,
                            const float* __restrict__ Bp, const float* __restrict__ Dp,
                            int ldz, int hd, int gx, int gy, int nsplit, int H,
                            int klen, int ldc,
                            int ltid, int wg, int grp, int ngrp, float* gsm)
{
    float* Asb = gsm;             // 1088
    float* Zs  = gsm + 1088;      // 2*1088
    float* Ex  = gsm + 3264;      // 192
    const int tx = ltid & 15, ty = ltid >> 4;
    const int zrow = ltid >> 4, zf4 = ltid & 15;
    const int ail = ltid >> 4, aj4 = (ltid & 15) * 4;
    const int jobs_per_h = gx * gy * nsplit;
    const int njobs = H * jobs_per_h;
    const int nch = klen >> 4;

    for (int job = grp; job < njobs; job += ngrp) {
        const int h = job / jobs_per_h;
        int rem = job % jobs_per_h;
        const int z = rem / (gx * gy); rem %= gx * gy;
        const int by = rem / gx, bx = rem % gx;
        const int m0 = by * 64, ncol0 = h * hd + bx * 64, kstart = z * klen;
        const float* ss = ssrc + h * NNODES;
        const float* af = Af + h * NNODES;
        const float* cf = Cf + h * NNODES;

        wgsync(wg);
        if (ltid < 64) {
            int j = m0 + ltid;
            Ex[ltid]       = sdst[h * NNODES + j];
            Ex[64 + ltid]  = Bp[h * NNODES + j];
            Ex[128 + ltid] = Dp[h * NNODES + j];
        }

        const float* srcZ = Z + (size_t)(kstart + zrow) * ldz + ncol0 + zf4 * 4;
        const unsigned dstZ = su32(&Zs[zrow * 68 + zf4 * 4]);
        cpa16(dstZ, srcZ);           // chunk 0 -> buf 0
        cpcommit();

        float acc[4][4];
#pragma unroll
        for (int i = 0; i < 4; i++)
#pragma unroll
            for (int j = 0; j < 4; j++) acc[i][j] = 0.f;

        for (int c = 0; c < nch; c++) {
            const int cb = c & 1;
            if (c + 1 < nch) {
                cpa16(dstZ + (cb ^ 1) * 4352, srcZ + (size_t)(c + 1) * 16 * ldz);
                cpcommit();
            }
            // build alpha chunk c (smem Asb; Ex visible after the wgsync below
            // for c==0 via... Ex written before cpa16+this; need barrier before use)
            // NOTE: Ex was written above; the wgsync at loop top of compute covers it.
            {
                int ig = kstart + c * 16 + ail;
                float ssv = ss[ig], afv = af[ig], cfv = cf[ig];
                float4 w;
                float* exd = Ex, *exb = Ex + 64, *exD = Ex + 128;
                int jj = aj4;
                float x0 = ssv + exd[jj + 0];
                float x1 = ssv + exd[jj + 1];
                float x2 = ssv + exd[jj + 2];
                float x3 = ssv + exd[jj + 3];
                w.x = x0 > 0.f ? afv * exb[jj + 0] : cfv * exD[jj + 0];
                w.y = x1 > 0.f ? afv * exb[jj + 1] : cfv * exD[jj + 1];
                w.z = x2 > 0.f ? afv * exb[jj + 2] : cfv * exD[jj + 2];
                w.w = x3 > 0.f ? afv * exb[jj + 3] : cfv * exD[jj + 3];
                if (ig == m0 + jj + 0) w.x = 0.f;
                if (ig == m0 + jj + 1) w.y = 0.f;
                if (ig == m0 + jj + 2) w.z = 0.f;
                if (ig == m0 + jj + 3) w.w = 0.f;
                *(float4*)&Asb[ail * 68 + aj4] = w;
            }
            if (c + 1 < nch) cpwait1(); else cpwait0();
            wgsync(wg);

            const float* Zb = Zs + cb * 1088;
#pragma unroll
            for (int kk = 0; kk < 16; kk++) {
                float4 a = *(const float4*)&Asb[kk * 68 + ty * 4];
                float4 b = *(const float4*)&Zb[kk * 68 + tx * 4];
                float a4[4] = {a.x, a.y, a.z, a.w};
                float b4[4] = {b.x, b.y, b.z, b.w};
#pragma unroll
                for (int i = 0; i < 4; i++)
#pragma unroll
                    for (int j = 0; j < 4; j++) acc[i][j] += a4[i] * b4[j];
            }
            wgsync(wg);
        }

        float* outp = C + (size_t)z * NNODES * ldc;
#pragma unroll
        for (int i = 0; i < 4; i++)
#pragma unroll
            for (int j = 0; j < 4; j++)
                outp[(size_t)(m0 + ty * 4 + i) * ldc + ncol0 + tx * 4 + j] = acc[i][j];
    }
}

// NOTE on Ex visibility: Ex is written right before the chunk-0 cp.async; the first
// alpha construction reads Ex in the same iteration. Protect with a wgsync before
// the loop. (Done below via explicit barrier after Ex store.)

// ----------------------------------------------------------------------------
// Combine k-split partials
// ----------------------------------------------------------------------------
__device__ void ph_combine(float* __restrict__ out, const float* __restrict__ part,
                           int nparts, int total, int ncols,
                           const float* __restrict__ bias, int act)
{
    for (int idx = blockIdx.x * NT + threadIdx.x; idx < total; idx += gridDim.x * NT) {
        float s = 0.f;
        for (int p = 0; p < nparts; p++) s += part[(size_t)p * total + idx];
        if (bias) s += bias[idx % ncols];
        if (act == 1) s = fmaxf(s, 0.f);
        else if (act == 2) s = s > 0.f ? s : expm1f(s);
        out[idx] = s;
    }
}

// ----------------------------------------------------------------------------
// Attention scores: warp per (h, i)
// ----------------------------------------------------------------------------
__device__ void ph_scores(const float* __restrict__ z, int ldz,
                          const float* __restrict__ a, int D,
                          float* __restrict__ ssrc, float* __restrict__ sdst, int H)
{
    const int lane = threadIdx.x & 31;
    const int gw = blockIdx.x * (NT / 32) + (threadIdx.x >> 5);
    const int nw = gridDim.x * (NT / 32);
    for (int w = gw; w < H * NNODES; w += nw) {
        int h = w / NNODES, i = w % NNODES;
        const float* zr = z + (size_t)i * ldz + h * D;
        const float* ar = a + (size_t)h * 2 * D;
        float s1 = 0.f, s2 = 0.f;
        for (int d = lane; d < D; d += 32) {
            float v = zr[d];
            s1 += v * ar[d];
            s2 += v * ar[D + d];
        }
#pragma unroll
        for (int o = 16; o; o >>= 1) {
            s1 += __shfl_xor_sync(0xffffffffu, s1, o);
            s2 += __shfl_xor_sync(0xffffffffu, s2, o);
        }
        if (lane == 0) { ssrc[h * NNODES + i] = s1; sdst[h * NNODES + i] = s2; }
    }
}

// ----------------------------------------------------------------------------
// Separable-softmax stats (as R6): warpgroup per (h, 64-j chunk)
// ----------------------------------------------------------------------------
__device__ void ph_stats(const float* __restrict__ ssrc, const float* __restrict__ sdst,
                         float* __restrict__ Af, float* __restrict__ Cf,
                         float* __restrict__ Bpg, float* __restrict__ Dpg,
                         int H, int ltid, int wg, int grp, int ngrp, float* gsm)
{
    float* ss  = gsm;
    float* aa  = gsm + 512;
    float* cc  = gsm + 1024;
    float* rm1 = gsm + 1536;
    float* rm2 = gsm + 1792;
    int*   ri1 = (int*)(gsm + 2048);
    const int cpj = NNODES / 64;
    const int njobs = H * cpj;

    for (int job = grp; job < njobs; job += ngrp) {
        const int h = job / cpj, jc = job % cpj;
        wgsync(wg);
        for (int i = ltid; i < NNODES; i += GSZ) ss[i] = ssrc[h * NNODES + i];
        wgsync(wg);

        float m1 = -1e30f, m2 = -1e30f; int i1 = -1;
        for (int i = ltid; i < NNODES; i += GSZ) {
            float v = ss[i];
            if (v > m1) { m2 = m1; m1 = v; i1 = i; }
            else if (v > m2) m2 = v;
        }
        rm1[ltid] = m1; rm2[ltid] = m2; ri1[ltid] = i1;
        wgsync(wg);
        if (ltid < 32) {
            float a1 = rm1[ltid], a2 = rm2[ltid]; int ai = ri1[ltid];
            for (int t = ltid + 32; t < GSZ; t += 32) {
                float b1 = rm1[t], b2 = rm2[t];
                if (b1 > a1) { a2 = fmaxf(a1, b2); a1 = b1; ai = ri1[t]; }
                else         { a2 = fmaxf(a2, b1); }
            }
            rm1[ltid] = a1; rm2[ltid] = a2; ri1[ltid] = ai;
        }
        wgsync(wg);
        if (ltid == 0) {
            float a1 = rm1[0], a2 = rm2[0]; int ai = ri1[0];
            for (int t = 1; t < 32; t++) {
                float b1 = rm1[t], b2 = rm2[t];
                if (b1 > a1) { a2 = fmaxf(a1, b2); a1 = b1; ai = ri1[t]; }
                else         { a2 = fmaxf(a2, b1); }
            }
            rm1[0] = a1; rm2[0] = a2; ri1[0] = ai;
        }
        wgsync(wg);
        const float Ms = rm1[0], M2 = rm2[0];
        const int iarg = ri1[0];

        for (int i = ltid; i < NNODES; i += GSZ) {
            float d = ss[i] - Ms;
            aa[i] = __expf(d);
            cc[i] = __expf(0.01f * d);
        }
        wgsync(wg);
        if (jc == 0) {
            for (int i = ltid; i < NNODES; i += GSZ) {
                Af[h * NNODES + i] = aa[i];
                Cf[h * NNODES + i] = cc[i];
            }
        }

        const int wid = ltid >> 5, lane = ltid & 31;
        for (int jj = wid; jj < 64; jj += 8) {
            int j = jc * 64 + jj;
            float sd = sdst[h * NNODES + j];
            float smx = (j == iarg) ? M2 : Ms;
            float t0 = smx + sd;
            float mxj = t0 > 0.f ? t0 : 0.01f * t0;
            float Bj = __expf(Ms + sd - mxj);
            float Dj = __expf(0.01f * (Ms + sd) - mxj);
            float ssum = 0.f;
            for (int i = lane; i < NNODES; i += 32) {
                if (i == j) continue;
                float x = ss[i] + sd;
                ssum += (x > 0.f) ? aa[i] * Bj : cc[i] * Dj;
            }
#pragma unroll
            for (int o = 16; o; o >>= 1) ssum += __shfl_xor_sync(0xffffffffu, ssum, o);
            if (lane == 0) {
                float inv = 1.f / ssum;
                Bpg[h * NNODES + j] = Bj * inv;
                Dpg[h * NNODES + j] = Dj * inv;
            }
        }
    }
}

// ----------------------------------------------------------------------------
// Column softmax stats
// ----------------------------------------------------------------------------
__device__ void ph_colstats(const float* __restrict__ h2,
                            float* __restrict__ mxc, float* __restrict__ invc,
                            int ltid, int wg, int grp, int ngrp, float* gsm)
{
    float* red  = gsm;
    float* red2 = gsm + 256;
    const int fl = ltid & 63, rg = ltid >> 6;
    for (int job = grp; job < IND / 64; job += ngrp) {
        const int f = job * 64 + fl;
        wgsync(wg);
        float m = -1e30f;
        for (int r0 = rg; r0 < NNODES; r0 += 4) m = fmaxf(m, h2[(size_t)r0 * IND + f]);
        red[rg * 64 + fl] = m;
        wgsync(wg);
        if (rg == 0)
            red[fl] = fmaxf(fmaxf(red[fl], red[64 + fl]), fmaxf(red[128 + fl], red[192 + fl]));
        wgsync(wg);
        const float mf = red[fl];
        float s = 0.f;
        for (int r0 = rg; r0 < NNODES; r0 += 4) s += __expf(h2[(size_t)r0 * IND + f] - mf);
        red2[rg * 64 + fl] = s;
        wgsync(wg);
        if (rg == 0) {
            float t = red2[fl] + red2[64 + fl] + red2[128 + fl] + red2[192 + fl];
            mxc[f] = mf;
            invc[f] = 1.f / t;
        }
    }
}

// ----------------------------------------------------------------------------
// p = softmax(h2, axis=0)
// ----------------------------------------------------------------------------
__device__ void ph_pmat(const float* __restrict__ h2, const float* __restrict__ mxc,
                        const float* __restrict__ invc, float* __restrict__ p)
{
    const int total4 = NNODES * IND / 4;
    for (int q = blockIdx.x * NT + threadIdx.x; q < total4; q += gridDim.x * NT) {
        int idx = q * 4;
        int c = idx % IND;
        float4 v  = *(const float4*)&h2[idx];
        float4 mx = *(const float4*)&mxc[c];
        float4 iv = *(const float4*)&invc[c];
        float4 o;
        o.x = __expf(v.x - mx.x) * iv.x;
        o.y = __expf(v.y - mx.y) * iv.y;
        o.z = __expf(v.z - mx.z) * iv.z;
        o.w = __expf(v.w - mx.w) * iv.w;
        *(float4*)&p[idx] = o;
    }
}

// ----------------------------------------------------------------------------
// Column sum + fc2
// ----------------------------------------------------------------------------
__device__ void ph_colsum(const float* __restrict__ r, float* __restrict__ rsum,
                          int ltid, int wg, int grp, int ngrp, float* gsm)
{
    const int cl = ltid & 31, rg = ltid >> 5;
    for (int job = grp; job < KCC / 32; job += ngrp) {
        const int c = job * 32 + cl;
        wgsync(wg);
        float s = 0.f;
        for (int r0 = rg; r0 < NNODES; r0 += 8) s += r[(size_t)r0 * KCC + c];
        gsm[rg * 32 + cl] = s;
        wgsync(wg);
        if (rg == 0) {
            float t = 0.f;
            for (int g = 0; g < 8; g++) t += gsm[g * 32 + cl];
            rsum[c] = t;
        }
    }
}

__device__ void ph_fc2(const float* __restrict__ rsum, const float* __restrict__ w,
                       const float* __restrict__ b, float* __restrict__ out)
{
    const int lane = threadIdx.x & 31;
    const int gw = blockIdx.x * (NT / 32) + (threadIdx.x >> 5);
    const int nw = gridDim.x * (NT / 32);
    for (int o = gw; o < OUTDIM; o += nw) {
        float s = 0.f;
        for (int k = lane; k < KCC; k += 32) s += rsum[k] * w[(size_t)o * KCC + k];
#pragma unroll
        for (int of = 16; of; of >>= 1) s += __shfl_xor_sync(0xffffffffu, s, of);
        if (lane == 0) out[o] = (float)NNODES * b[o] + s;
    }
}

// ----------------------------------------------------------------------------
// Persistent mega-kernel
// ----------------------------------------------------------------------------
__global__ void __launch_bounds__(NT, 1)
gat_mega(const float* __restrict__ X,  const float* __restrict__ W1,
         const float* __restrict__ a1, const float* __restrict__ W2,
         const float* __restrict__ a2, const float* __restrict__ fc1w,
         const float* __restrict__ fc1b, const float* __restrict__ fc2w,
         const float* __restrict__ fc2b, float* __restrict__ out)
{
    __shared__ float sm[NG * SMG];
    const int wg = threadIdx.x >> 8;
    const int ltid = threadIdx.x & 255;
    float* gsm = sm + wg * SMG;
    const int grp = blockIdx.x * NG + wg;
    const int ngrp = gridDim.x * NG;

    // P0: z1 partials = X @ W1^T, K=768 split 12 (384 jobs)
    ph_gemm_abt(X, W1, g_part, HD1, IND, 64, HD1 / 64, NNODES / 64, 12,
                ltid, wg, grp, ngrp, gsm);
    gridbar();
    // P1: combine -> z1
    ph_combine(g_z1, g_part, 12, NNODES * HD1, HD1, nullptr, 0);
    gridbar();
    // P2: layer1 scores
    ph_scores(g_z1, HD1, a1, HIDD, g_ssrc, g_sdst, NHEAD);
    gridbar();
    // P3: layer1 stats
    ph_stats(g_ssrc, g_sdst, g_Af, g_Cf, g_Bp, g_Dp, NHEAD, ltid, wg, grp, ngrp, gsm);
    gridbar();
    // P4: agg1 partials, split 8 (256 jobs)
    ph_gemm_agg(g_z1, g_part, g_ssrc, g_sdst, g_Af, g_Cf, g_Bp, g_Dp,
                HD1, HIDD, 1, NNODES / 64, 8, NHEAD, 64, HD1,
                ltid, wg, grp, ngrp, gsm);
    gridbar();
    // P5: combine + ELU -> h1
    ph_combine(g_h1, g_part, 8, NNODES * HD1, HD1, nullptr, 2);
    gridbar();
    // P6: z2 partials = h1 @ W2^T, K=256 split 4 (384 jobs)
    ph_gemm_abt(g_h1, W2, g_part, IND, HD1, 64, IND / 64, NNODES / 64, 4,
                ltid, wg, grp, ngrp, gsm);
    gridbar();
    // P6b: combine -> z2
    ph_combine(g_z2, g_part, 4, NNODES * IND, IND, nullptr, 0);
    gridbar();
    // P7: layer2 scores
    ph_scores(g_z2, IND, a2, IND, g_ssrc, g_sdst, 1);
    gridbar();
    // P8: layer2 stats
    ph_stats(g_ssrc, g_sdst, g_Af, g_Cf, g_Bp, g_Dp, 1, ltid, wg, grp, ngrp, gsm);
    gridbar();
    // P9: agg2 partials, split 4 (384 jobs)
    ph_gemm_agg(g_z2, g_part, g_ssrc, g_sdst, g_Af, g_Cf, g_Bp, g_Dp,
                IND, 0, IND / 64, NNODES / 64, 4, 1, 128, IND,
                ltid, wg, grp, ngrp, gsm);
    gridbar();
    // P10: combine -> h2
    ph_combine(g_h2, g_part, 4, NNODES * IND, IND, nullptr, 0);
    gridbar();
    // P11: column softmax stats
    ph_colstats(g_h2, g_mxc, g_invc, ltid, wg, grp, ngrp, gsm);
    gridbar();
    // P12: p = softmax(h2, axis=0)
    ph_pmat(g_h2, g_mxc, g_invc, g_p);
    gridbar();
    // P13: fc1 partials = p @ fc1_w^T, K=768 split 16 (384 jobs)
    ph_gemm_abt(g_p, fc1w, g_part, KCC, IND, 48, KCC / 64, NNODES / 64, 16,
                ltid, wg, grp, ngrp, gsm);
    gridbar();
    // P14: combine + bias + relu -> r
    ph_combine(g_r, g_part, 16, NNODES * KCC, KCC, fc1b, 1);
    gridbar();
    // P15: column sum -> rsum
    ph_colsum(g_r, g_rsum, ltid, wg, grp, ngrp, gsm);
    gridbar();
    // P16: fc2 -> out
    ph_fc2(g_rsum, fc2w, fc2b, out);
}

// ----------------------------------------------------------------------------
// Launch
// ----------------------------------------------------------------------------
extern "C" void kernel_launch(void* const* d_in, const int* in_sizes, int n_in,
                              void* d_out, int out_size)
{
    const float* X     = (const float*)d_in[0];
    const float* W1    = (const float*)d_in[1];
    const float* a1    = (const float*)d_in[2];
    const float* W2    = (const float*)d_in[3];
    const float* a2    = (const float*)d_in[4];
    const float* fc1_w = (const float*)d_in[5];
    const float* fc1_b = (const float*)d_in[6];
    const float* fc2_w = (const float*)d_in[7];
    const float* fc2_b = (const float*)d_in[8];

    int sms = 148;
    cudaDeviceGetAttribute(&sms, cudaDevAttrMultiProcessorCount, 0);

    gat_mega<<<sms, NT>>>(X, W1, a1, W2, a2, fc1_w, fc1_b, fc2_w, fc2_b, (float*)d_out);
}

// round 8
// speedup vs baseline: 1.3116x; 1.0351x over previous
#include <cuda_runtime.h>
#include <math.h>

#define NNODES 512
#define IND    768
#define HIDD   64
#define NHEAD  4
#define HD1    256
#define KCC    192
#define OUTDIM 256
#define NT     768          // threads per CTA
#define NG     3            // warpgroups per CTA
#define GSZ    256
#define SMG    5120         // smem floats per warpgroup
#define RS     20           // abt smem row stride (16 k + 4 pad)

// ----------------------------------------------------------------------------
// Device scratch
// ----------------------------------------------------------------------------
__device__ float g_z1[NNODES * HD1];
__device__ float g_h1[NNODES * HD1];
__device__ float g_z2[NNODES * IND];
__device__ float g_h2[NNODES * IND];
__device__ float g_p [NNODES * IND];
__device__ float g_r [NNODES * KCC];
__device__ float g_part[4 * NNODES * IND];        // 1.57M floats partial-K buffer
__device__ float g_ssrc[NHEAD * NNODES], g_sdst[NHEAD * NNODES];
__device__ float g_Af[NHEAD * NNODES], g_Cf[NHEAD * NNODES];
__device__ float g_Bp[NHEAD * NNODES], g_Dp[NHEAD * NNODES];
__device__ float g_mxc[IND], g_invc[IND];
__device__ float g_rsum[KCC];
__device__ unsigned g_barcnt = 0;
__device__ volatile unsigned g_bargen = 0;

// ----------------------------------------------------------------------------
// Barriers + cp.async helpers
// ----------------------------------------------------------------------------
__device__ __forceinline__ void wgsync(int wg) {
    asm volatile("bar.sync %0, %1;" :: "r"(wg + 1), "n"(GSZ) : "memory");
}

__device__ __forceinline__ void gridbar() {
    __syncthreads();
    if (threadIdx.x == 0) {
        __threadfence();
        unsigned gen = g_bargen;
        unsigned t = atomicAdd(&g_barcnt, 1u);
        if (t == gridDim.x - 1) {
            g_barcnt = 0;
            __threadfence();
            atomicAdd((unsigned*)&g_bargen, 1u);
        } else {
            while (g_bargen == gen) { __nanosleep(32); }
        }
        __threadfence();
    }
    __syncthreads();
}

__device__ __forceinline__ unsigned su32(const void* p) {
    return (unsigned)__cvta_generic_to_shared(p);
}
__device__ __forceinline__ void cpa16(unsigned d, const void* s) {
    asm volatile("cp.async.cg.shared.global [%0], [%1], 16;" :: "r"(d), "l"(s));
}
__device__ __forceinline__ void cpcommit() { asm volatile("cp.async.commit_group;"); }
__device__ __forceinline__ void cpwait0()  { asm volatile("cp.async.wait_group 0;"); }

// ----------------------------------------------------------------------------
// Pipelined SGEMM, chunk=16, ONE barrier per chunk.
// Cpart[z][512,Ncols] = A[512,K_ld] @ B[Ncols,K_ld]^T over k-split z.
// smem per group: As[2][64][RS], Bs[2][64][RS].
// ----------------------------------------------------------------------------
__device__ void ph_gemm_abt(const float* __restrict__ A, const float* __restrict__ B,
                            float* __restrict__ C, int Ncols, int K_ld, int klen,
                            int gx, int gy, int nsplit,
                            int ltid, int wg, int grp, int ngrp, float* gsm)
{
    float* As = gsm;                 // 2 * 1280
    float* Bs = gsm + 2560;          // 2 * 1280
    const int tx = ltid & 15, ty = ltid >> 4;
    const int isB  = ltid >> 7;
    const int lrow = (ltid & 127) >> 1;
    const int lh   = ltid & 1;               // which half of the 16-k chunk
    const int njobs = gx * gy * nsplit;
    const int nch = klen >> 4;

    for (int job = grp; job < njobs; job += ngrp) {
        const int z = job / (gx * gy);
        const int rem = job % (gx * gy);
        const int by = rem / gx, bx = rem % gx;
        const int m0 = by * 64, n0 = bx * 64, kstart = z * klen;

        const float* src0 = isB ? (B + (size_t)(n0 + lrow) * K_ld + kstart + lh * 8)
                                : (A + (size_t)(m0 + lrow) * K_ld + kstart + lh * 8);
        const unsigned dst0 = isB ? su32(&Bs[lrow * RS + lh * 8])
                                  : su32(&As[lrow * RS + lh * 8]);

        float acc[4][4];
#pragma unroll
        for (int i = 0; i < 4; i++)
#pragma unroll
            for (int j = 0; j < 4; j++) acc[i][j] = 0.f;

        wgsync(wg);                  // guard smem reuse across jobs (odd nch safe)
        cpa16(dst0, src0);
        cpa16(dst0 + 16, src0 + 4);
        cpcommit();

        for (int c = 0; c < nch; c++) {
            const int cb = c & 1;
            cpwait0();               // chunk c arrived (only group outstanding)
            wgsync(wg);              // all threads done with buf cb^1
            if (c + 1 < nch) {
                const unsigned d = dst0 + (cb ^ 1) * 5120;   // 1280 floats
                const float* s = src0 + (c + 1) * 16;
                cpa16(d, s);
                cpa16(d + 16, s + 4);
                cpcommit();
            }
            const float* Ab = As + cb * 1280;
            const float* Bb = Bs + cb * 1280;
#pragma unroll
            for (int q = 0; q < 4; q++) {
                float4 af[4], bf[4];
#pragma unroll
                for (int i = 0; i < 4; i++)
                    af[i] = *(const float4*)&Ab[(ty + 16 * i) * RS + q * 4];
#pragma unroll
                for (int j = 0; j < 4; j++)
                    bf[j] = *(const float4*)&Bb[(tx + 16 * j) * RS + q * 4];
#pragma unroll
                for (int i = 0; i < 4; i++)
#pragma unroll
                    for (int j = 0; j < 4; j++) {
                        acc[i][j] += af[i].x * bf[j].x;
                        acc[i][j] += af[i].y * bf[j].y;
                        acc[i][j] += af[i].z * bf[j].z;
                        acc[i][j] += af[i].w * bf[j].w;
                    }
            }
        }

        float* outp = C + (size_t)z * NNODES * Ncols;
#pragma unroll
        for (int i = 0; i < 4; i++)
#pragma unroll
            for (int j = 0; j < 4; j++)
                outp[(size_t)(m0 + ty + 16 * i) * Ncols + n0 + tx + 16 * j] = acc[i][j];
    }
}

// ----------------------------------------------------------------------------
// Pipelined aggregation GEMM, chunk=16, ONE barrier per chunk.
// alpha[j][i] = (i!=j)*sel(ss[i]+d[j]>0, Af[i]*Bp[j], Cf[i]*Dp[j]) built into
// double-buffered smem; Z streamed via cp.async.
// smem per group: Asb[2][16][68], Zs[2][16][68], Ex[192].
// ----------------------------------------------------------------------------
__device__ void ph_gemm_agg(const float* __restrict__ Z, float* __restrict__ C,
                            const float* __restrict__ ssrc, const float* __restrict__ sdst,
                            const float* __restrict__ Af, const float* __restrict__ Cf,
                            const float* __restrict__ Bp, const float* __restrict__ Dp,
                            int ldz, int hd, int gx, int gy, int nsplit, int H,
                            int klen, int ldc,
                            int ltid, int wg, int grp, int ngrp, float* gsm)
{
    float* Asb = gsm;              // 2 * 1088
    float* Zs  = gsm + 2176;       // 2 * 1088
    float* Ex  = gsm + 4352;       // 192
    const int tx = ltid & 15, ty = ltid >> 4;
    const int zrow = ltid >> 4, zf4 = ltid & 15;
    const int ail = ltid >> 4, aj4 = (ltid & 15) * 4;
    const int jobs_per_h = gx * gy * nsplit;
    const int njobs = H * jobs_per_h;
    const int nch = klen >> 4;

    for (int job = grp; job < njobs; job += ngrp) {
        const int h = job / jobs_per_h;
        int rem = job % jobs_per_h;
        const int z = rem / (gx * gy); rem %= gx * gy;
        const int by = rem / gx, bx = rem % gx;
        const int m0 = by * 64, ncol0 = h * hd + bx * 64, kstart = z * klen;
        const float* ss = ssrc + h * NNODES;
        const float* af = Af + h * NNODES;
        const float* cf = Cf + h * NNODES;

        auto build = [&](int cc, float* dst) {
            int ig = kstart + cc * 16 + ail;
            float ssv = ss[ig], afv = af[ig], cfv = cf[ig];
            float* exd = Ex; float* exb = Ex + 64; float* exD = Ex + 128;
            int jj = aj4;
            float4 w;
            float x0 = ssv + exd[jj + 0];
            float x1 = ssv + exd[jj + 1];
            float x2 = ssv + exd[jj + 2];
            float x3 = ssv + exd[jj + 3];
            w.x = x0 > 0.f ? afv * exb[jj + 0] : cfv * exD[jj + 0];
            w.y = x1 > 0.f ? afv * exb[jj + 1] : cfv * exD[jj + 1];
            w.z = x2 > 0.f ? afv * exb[jj + 2] : cfv * exD[jj + 2];
            w.w = x3 > 0.f ? afv * exb[jj + 3] : cfv * exD[jj + 3];
            if (ig == m0 + jj + 0) w.x = 0.f;
            if (ig == m0 + jj + 1) w.y = 0.f;
            if (ig == m0 + jj + 2) w.z = 0.f;
            if (ig == m0 + jj + 3) w.w = 0.f;
            *(float4*)&dst[ail * 68 + aj4] = w;
        };

        wgsync(wg);                         // job-start: smem safe to overwrite
        if (ltid < 64) {
            int j = m0 + ltid;
            Ex[ltid]       = sdst[h * NNODES + j];
            Ex[64 + ltid]  = Bp[h * NNODES + j];
            Ex[128 + ltid] = Dp[h * NNODES + j];
        }
        wgsync(wg);                         // Ex visible to ALL threads (race fix)

        build(0, Asb);                      // alpha chunk 0 -> Asb buf 0
        const float* srcZ = Z + (size_t)(kstart + zrow) * ldz + ncol0 + zf4 * 4;
        const unsigned dstZ = su32(&Zs[zrow * 68 + zf4 * 4]);
        cpa16(dstZ, srcZ);                  // Z chunk 0 -> Zs buf 0
        cpcommit();

        float acc[4][4];
#pragma unroll
        for (int i = 0; i < 4; i++)
#pragma unroll
            for (int j = 0; j < 4; j++) acc[i][j] = 0.f;

        for (int c = 0; c < nch; c++) {
            const int cb = c & 1;
            cpwait0();                      // Z chunk c arrived
            wgsync(wg);                     // prev compute done; builds visible
            if (c + 1 < nch) {
                cpa16(dstZ + (cb ^ 1) * 4352, srcZ + (size_t)(c + 1) * 16 * ldz);
                cpcommit();
                build(c + 1, Asb + (cb ^ 1) * 1088);
            }
            const float* Ab = Asb + cb * 1088;
            const float* Zb = Zs  + cb * 1088;
#pragma unroll
            for (int kk = 0; kk < 16; kk++) {
                float4 a = *(const float4*)&Ab[kk * 68 + ty * 4];
                float4 b = *(const float4*)&Zb[kk * 68 + tx * 4];
                float a4[4] = {a.x, a.y, a.z, a.w};
                float b4[4] = {b.x, b.y, b.z, b.w};
#pragma unroll
                for (int i = 0; i < 4; i++)
#pragma unroll
                    for (int j = 0; j < 4; j++) acc[i][j] += a4[i] * b4[j];
            }
        }

        float* outp = C + (size_t)z * NNODES * ldc;
#pragma unroll
        for (int i = 0; i < 4; i++)
#pragma unroll
            for (int j = 0; j < 4; j++)
                outp[(size_t)(m0 + ty * 4 + i) * ldc + ncol0 + tx * 4 + j] = acc[i][j];
    }
}

// ----------------------------------------------------------------------------
// Combine k-split partials
// ----------------------------------------------------------------------------
__device__ void ph_combine(float* __restrict__ out, const float* __restrict__ part,
                           int nparts, int total, int ncols,
                           const float* __restrict__ bias, int act)
{
    for (int idx = blockIdx.x * NT + threadIdx.x; idx < total; idx += gridDim.x * NT) {
        float s = 0.f;
        for (int p = 0; p < nparts; p++) s += part[(size_t)p * total + idx];
        if (bias) s += bias[idx % ncols];
        if (act == 1) s = fmaxf(s, 0.f);
        else if (act == 2) s = s > 0.f ? s : expm1f(s);
        out[idx] = s;
    }
}

// ----------------------------------------------------------------------------
// Attention scores: warp per (h, i)
// ----------------------------------------------------------------------------
__device__ void ph_scores(const float* __restrict__ z, int ldz,
                          const float* __restrict__ a, int D,
                          float* __restrict__ ssrc, float* __restrict__ sdst, int H)
{
    const int lane = threadIdx.x & 31;
    const int gw = blockIdx.x * (NT / 32) + (threadIdx.x >> 5);
    const int nw = gridDim.x * (NT / 32);
    for (int w = gw; w < H * NNODES; w += nw) {
        int h = w / NNODES, i = w % NNODES;
        const float* zr = z + (size_t)i * ldz + h * D;
        const float* ar = a + (size_t)h * 2 * D;
        float s1 = 0.f, s2 = 0.f;
        for (int d = lane; d < D; d += 32) {
            float v = zr[d];
            s1 += v * ar[d];
            s2 += v * ar[D + d];
        }
#pragma unroll
        for (int o = 16; o; o >>= 1) {
            s1 += __shfl_xor_sync(0xffffffffu, s1, o);
            s2 += __shfl_xor_sync(0xffffffffu, s2, o);
        }
        if (lane == 0) { ssrc[h * NNODES + i] = s1; sdst[h * NNODES + i] = s2; }
    }
}

// ----------------------------------------------------------------------------
// Separable-softmax stats: warpgroup per (h, 64-j chunk)
// ----------------------------------------------------------------------------
__device__ void ph_stats(const float* __restrict__ ssrc, const float* __restrict__ sdst,
                         float* __restrict__ Af, float* __restrict__ Cf,
                         float* __restrict__ Bpg, float* __restrict__ Dpg,
                         int H, int ltid, int wg, int grp, int ngrp, float* gsm)
{
    float* ss  = gsm;
    float* aa  = gsm + 512;
    float* cc  = gsm + 1024;
    float* rm1 = gsm + 1536;
    float* rm2 = gsm + 1792;
    int*   ri1 = (int*)(gsm + 2048);
    const int cpj = NNODES / 64;
    const int njobs = H * cpj;

    for (int job = grp; job < njobs; job += ngrp) {
        const int h = job / cpj, jc = job % cpj;
        wgsync(wg);
        for (int i = ltid; i < NNODES; i += GSZ) ss[i] = ssrc[h * NNODES + i];
        wgsync(wg);

        float m1 = -1e30f, m2 = -1e30f; int i1 = -1;
        for (int i = ltid; i < NNODES; i += GSZ) {
            float v = ss[i];
            if (v > m1) { m2 = m1; m1 = v; i1 = i; }
            else if (v > m2) m2 = v;
        }
        rm1[ltid] = m1; rm2[ltid] = m2; ri1[ltid] = i1;
        wgsync(wg);
        if (ltid < 32) {
            float a1 = rm1[ltid], a2 = rm2[ltid]; int ai = ri1[ltid];
            for (int t = ltid + 32; t < GSZ; t += 32) {
                float b1 = rm1[t], b2 = rm2[t];
                if (b1 > a1) { a2 = fmaxf(a1, b2); a1 = b1; ai = ri1[t]; }
                else         { a2 = fmaxf(a2, b1); }
            }
            rm1[ltid] = a1; rm2[ltid] = a2; ri1[ltid] = ai;
        }
        wgsync(wg);
        if (ltid == 0) {
            float a1 = rm1[0], a2 = rm2[0]; int ai = ri1[0];
            for (int t = 1; t < 32; t++) {
                float b1 = rm1[t], b2 = rm2[t];
                if (b1 > a1) { a2 = fmaxf(a1, b2); a1 = b1; ai = ri1[t]; }
                else         { a2 = fmaxf(a2, b1); }
            }
            rm1[0] = a1; rm2[0] = a2; ri1[0] = ai;
        }
        wgsync(wg);
        const float Ms = rm1[0], M2 = rm2[0];
        const int iarg = ri1[0];

        for (int i = ltid; i < NNODES; i += GSZ) {
            float d = ss[i] - Ms;
            aa[i] = __expf(d);
            cc[i] = __expf(0.01f * d);
        }
        wgsync(wg);
        if (jc == 0) {
            for (int i = ltid; i < NNODES; i += GSZ) {
                Af[h * NNODES + i] = aa[i];
                Cf[h * NNODES + i] = cc[i];
            }
        }

        const int wid = ltid >> 5, lane = ltid & 31;
        for (int jj = wid; jj < 64; jj += 8) {
            int j = jc * 64 + jj;
            float sd = sdst[h * NNODES + j];
            float smx = (j == iarg) ? M2 : Ms;
            float t0 = smx + sd;
            float mxj = t0 > 0.f ? t0 : 0.01f * t0;
            float Bj = __expf(Ms + sd - mxj);
            float Dj = __expf(0.01f * (Ms + sd) - mxj);
            float ssum = 0.f;
            for (int i = lane; i < NNODES; i += 32) {
                if (i == j) continue;
                float x = ss[i] + sd;
                ssum += (x > 0.f) ? aa[i] * Bj : cc[i] * Dj;
            }
#pragma unroll
            for (int o = 16; o; o >>= 1) ssum += __shfl_xor_sync(0xffffffffu, ssum, o);
            if (lane == 0) {
                float inv = 1.f / ssum;
                Bpg[h * NNODES + j] = Bj * inv;
                Dpg[h * NNODES + j] = Dj * inv;
            }
        }
    }
}

// ----------------------------------------------------------------------------
// Column softmax stats
// ----------------------------------------------------------------------------
__device__ void ph_colstats(const float* __restrict__ h2,
                            float* __restrict__ mxc, float* __restrict__ invc,
                            int ltid, int wg, int grp, int ngrp, float* gsm)
{
    float* red  = gsm;
    float* red2 = gsm + 256;
    const int fl = ltid & 63, rg = ltid >> 6;
    for (int job = grp; job < IND / 64; job += ngrp) {
        const int f = job * 64 + fl;
        wgsync(wg);
        float m = -1e30f;
        for (int r0 = rg; r0 < NNODES; r0 += 4) m = fmaxf(m, h2[(size_t)r0 * IND + f]);
        red[rg * 64 + fl] = m;
        wgsync(wg);
        if (rg == 0)
            red[fl] = fmaxf(fmaxf(red[fl], red[64 + fl]), fmaxf(red[128 + fl], red[192 + fl]));
        wgsync(wg);
        const float mf = red[fl];
        float s = 0.f;
        for (int r0 = rg; r0 < NNODES; r0 += 4) s += __expf(h2[(size_t)r0 * IND + f] - mf);
        red2[rg * 64 + fl] = s;
        wgsync(wg);
        if (rg == 0) {
            float t = red2[fl] + red2[64 + fl] + red2[128 + fl] + red2[192 + fl];
            mxc[f] = mf;
            invc[f] = 1.f / t;
        }
    }
}

// ----------------------------------------------------------------------------
// p = softmax(h2, axis=0)
// ----------------------------------------------------------------------------
__device__ void ph_pmat(const float* __restrict__ h2, const float* __restrict__ mxc,
                        const float* __restrict__ invc, float* __restrict__ p)
{
    const int total4 = NNODES * IND / 4;
    for (int q = blockIdx.x * NT + threadIdx.x; q < total4; q += gridDim.x * NT) {
        int idx = q * 4;
        int c = idx % IND;
        float4 v  = *(const float4*)&h2[idx];
        float4 mx = *(const float4*)&mxc[c];
        float4 iv = *(const float4*)&invc[c];
        float4 o;
        o.x = __expf(v.x - mx.x) * iv.x;
        o.y = __expf(v.y - mx.y) * iv.y;
        o.z = __expf(v.z - mx.z) * iv.z;
        o.w = __expf(v.w - mx.w) * iv.w;
        *(float4*)&p[idx] = o;
    }
}

// ----------------------------------------------------------------------------
// Column sum + fc2
// ----------------------------------------------------------------------------
__device__ void ph_colsum(const float* __restrict__ r, float* __restrict__ rsum,
                          int ltid, int wg, int grp, int ngrp, float* gsm)
{
    const int cl = ltid & 31, rg = ltid >> 5;
    for (int job = grp; job < KCC / 32; job += ngrp) {
        const int c = job * 32 + cl;
        wgsync(wg);
        float s = 0.f;
        for (int r0 = rg; r0 < NNODES; r0 += 8) s += r[(size_t)r0 * KCC + c];
        gsm[rg * 32 + cl] = s;
        wgsync(wg);
        if (rg == 0) {
            float t = 0.f;
            for (int g = 0; g < 8; g++) t += gsm[g * 32 + cl];
            rsum[c] = t;
        }
    }
}

__device__ void ph_fc2(const float* __restrict__ rsum, const float* __restrict__ w,
                       const float* __restrict__ b, float* __restrict__ out)
{
    const int lane = threadIdx.x & 31;
    const int gw = blockIdx.x * (NT / 32) + (threadIdx.x >> 5);
    const int nw = gridDim.x * (NT / 32);
    for (int o = gw; o < OUTDIM; o += nw) {
        float s = 0.f;
        for (int k = lane; k < KCC; k += 32) s += rsum[k] * w[(size_t)o * KCC + k];
#pragma unroll
        for (int of = 16; of; of >>= 1) s += __shfl_xor_sync(0xffffffffu, s, of);
        if (lane == 0) out[o] = (float)NNODES * b[o] + s;
    }
}

// ----------------------------------------------------------------------------
// Persistent mega-kernel (dynamic smem: NG*SMG floats)
// ----------------------------------------------------------------------------
__global__ void __launch_bounds__(NT, 1)
gat_mega(const float* __restrict__ X,  const float* __restrict__ W1,
         const float* __restrict__ a1, const float* __restrict__ W2,
         const float* __restrict__ a2, const float* __restrict__ fc1w,
         const float* __restrict__ fc1b, const float* __restrict__ fc2w,
         const float* __restrict__ fc2b, float* __restrict__ out)
{
    extern __shared__ float sm[];
    const int wg = threadIdx.x >> 8;
    const int ltid = threadIdx.x & 255;
    float* gsm = sm + wg * SMG;
    const int grp = blockIdx.x * NG + wg;
    const int ngrp = gridDim.x * NG;

    // P0: z1 partials = X @ W1^T, K=768 split 12 (384 jobs, klen 64)
    ph_gemm_abt(X, W1, g_part, HD1, IND, 64, HD1 / 64, NNODES / 64, 12,
                ltid, wg, grp, ngrp, gsm);
    gridbar();
    // P1: combine -> z1
    ph_combine(g_z1, g_part, 12, NNODES * HD1, HD1, nullptr, 0);
    gridbar();
    // P2: layer1 scores
    ph_scores(g_z1, HD1, a1, HIDD, g_ssrc, g_sdst, NHEAD);
    gridbar();
    // P3: layer1 stats
    ph_stats(g_ssrc, g_sdst, g_Af, g_Cf, g_Bp, g_Dp, NHEAD, ltid, wg, grp, ngrp, gsm);
    gridbar();
    // P4: agg1 partials, split 8 (256 jobs, klen 64)
    ph_gemm_agg(g_z1, g_part, g_ssrc, g_sdst, g_Af, g_Cf, g_Bp, g_Dp,
                HD1, HIDD, 1, NNODES / 64, 8, NHEAD, 64, HD1,
                ltid, wg, grp, ngrp, gsm);
    gridbar();
    // P5: combine + ELU -> h1
    ph_combine(g_h1, g_part, 8, NNODES * HD1, HD1, nullptr, 2);
    gridbar();
    // P6: z2 partials = h1 @ W2^T, K=256 split 4 (384 jobs, klen 64)
    ph_gemm_abt(g_h1, W2, g_part, IND, HD1, 64, IND / 64, NNODES / 64, 4,
                ltid, wg, grp, ngrp, gsm);
    gridbar();
    // P6b: combine -> z2
    ph_combine(g_z2, g_part, 4, NNODES * IND, IND, nullptr, 0);
    gridbar();
    // P7: layer2 scores
    ph_scores(g_z2, IND, a2, IND, g_ssrc, g_sdst, 1);
    gridbar();
    // P8: layer2 stats
    ph_stats(g_ssrc, g_sdst, g_Af, g_Cf, g_Bp, g_Dp, 1, ltid, wg, grp, ngrp, gsm);
    gridbar();
    // P9: agg2 partials, split 4 (384 jobs, klen 128)
    ph_gemm_agg(g_z2, g_part, g_ssrc, g_sdst, g_Af, g_Cf, g_Bp, g_Dp,
                IND, 0, IND / 64, NNODES / 64, 4, 1, 128, IND,
                ltid, wg, grp, ngrp, gsm);
    gridbar();
    // P10: combine -> h2
    ph_combine(g_h2, g_part, 4, NNODES * IND, IND, nullptr, 0);
    gridbar();
    // P11: column softmax stats
    ph_colstats(g_h2, g_mxc, g_invc, ltid, wg, grp, ngrp, gsm);
    gridbar();
    // P12: p = softmax(h2, axis=0)
    ph_pmat(g_h2, g_mxc, g_invc, g_p);
    gridbar();
    // P13: fc1 partials = p @ fc1_w^T, K=768 split 16 (384 jobs, klen 48)
    ph_gemm_abt(g_p, fc1w, g_part, KCC, IND, 48, KCC / 64, NNODES / 64, 16,
                ltid, wg, grp, ngrp, gsm);
    gridbar();
    // P14: combine + bias + relu -> r
    ph_combine(g_r, g_part, 16, NNODES * KCC, KCC, fc1b, 1);
    gridbar();
    // P15: column sum -> rsum
    ph_colsum(g_r, g_rsum, ltid, wg, grp, ngrp, gsm);
    gridbar();
    // P16: fc2 -> out
    ph_fc2(g_rsum, fc2w, fc2b, out);
}

// ----------------------------------------------------------------------------
// Launch
// ----------------------------------------------------------------------------
extern "C" void kernel_launch(void* const* d_in, const int* in_sizes, int n_in,
                              void* d_out, int out_size)
{
    const float* X     = (const float*)d_in[0];
    const float* W1    = (const float*)d_in[1];
    const float* a1    = (const float*)d_in[2];
    const float* W2    = (const float*)d_in[3];
    const float* a2    = (const float*)d_in[4];
    const float* fc1_w = (const float*)d_in[5];
    const float* fc1_b = (const float*)d_in[6];
    const float* fc2_w = (const float*)d_in[7];
    const float* fc2_b = (const float*)d_in[8];

    int sms = 148;
    cudaDeviceGetAttribute(&sms, cudaDevAttrMultiProcessorCount, 0);

    const size_t smbytes = (size_t)NG * SMG * sizeof(float);   // 60 KB
    cudaFuncSetAttribute(gat_mega, cudaFuncAttributeMaxDynamicSharedMemorySize,
                         (int)smbytes);

    gat_mega<<<sms, NT, smbytes>>>(X, W1, a1, W2, a2, fc1_w, fc1_b, fc2_w, fc2_b,
                                   (float*)d_out);
}

// round 9
// speedup vs baseline: 1.3164x; 1.0036x over previous
#include <cuda_runtime.h>
#include <math.h>

#define NNODES 512
#define IND    768
#define HIDD   64
#define NHEAD  4
#define HD1    256
#define KCC    192
#define OUTDIM 256
#define NT     768          // threads per CTA
#define NG     3            // warpgroups per CTA
#define GSZ    256
#define SMG    5120         // smem floats per warpgroup
#define RS     20           // abt smem row stride (16 k + 4 pad)

// ----------------------------------------------------------------------------
// Device scratch
// ----------------------------------------------------------------------------
__device__ float g_z1[NNODES * HD1];
__device__ float g_h1[NNODES * HD1];
__device__ float g_z2[NNODES * IND];
__device__ float g_h2[NNODES * IND];
__device__ float g_r [NNODES * KCC];
__device__ float g_part[4 * NNODES * IND];
__device__ float g_ssrc[NHEAD * NNODES], g_sdst[NHEAD * NNODES];
__device__ float g_Af[NHEAD * NNODES], g_Cf[NHEAD * NNODES];
__device__ float g_Bp[NHEAD * NNODES], g_Dp[NHEAD * NNODES];
__device__ float g_mxc[IND], g_invc[IND];
__device__ float g_rsum[KCC];
__device__ unsigned g_cnt8[8];
__device__ unsigned g_root = 0;
__device__ volatile unsigned g_bargen = 0;

// ----------------------------------------------------------------------------
// Barriers + cp.async helpers
// ----------------------------------------------------------------------------
__device__ __forceinline__ void wgsync(int wg) {
    asm volatile("bar.sync %0, %1;" :: "r"(wg + 1), "n"(GSZ) : "memory");
}

// Hierarchical grid barrier: 8 buckets -> root -> generation flip.
__device__ __forceinline__ void gridbar() {
    __syncthreads();
    if (threadIdx.x == 0) {
        __threadfence();
        const unsigned gen = g_bargen;
        const unsigned b = blockIdx.x & 7u;
        const unsigned bsz = (gridDim.x >> 3) + (((gridDim.x & 7u) > b) ? 1u : 0u);
        if (atomicAdd(&g_cnt8[b], 1u) == bsz - 1u) {
            atomicExch(&g_cnt8[b], 0u);
            __threadfence();
            if (atomicAdd(&g_root, 1u) == 7u) {
                atomicExch(&g_root, 0u);
                __threadfence();
                atomicAdd((unsigned*)&g_bargen, 1u);
            }
        }
        while (g_bargen == gen) { __nanosleep(32); }
        __threadfence();
    }
    __syncthreads();
}

__device__ __forceinline__ unsigned su32(const void* p) {
    return (unsigned)__cvta_generic_to_shared(p);
}
__device__ __forceinline__ void cpa16(unsigned d, const void* s) {
    asm volatile("cp.async.cg.shared.global [%0], [%1], 16;" :: "r"(d), "l"(s));
}
__device__ __forceinline__ void cpcommit() { asm volatile("cp.async.commit_group;"); }
__device__ __forceinline__ void cpwait0()  { asm volatile("cp.async.wait_group 0;"); }

// ----------------------------------------------------------------------------
// Pipelined SGEMM, chunk=16, one barrier per chunk.
// ----------------------------------------------------------------------------
__device__ void ph_gemm_abt(const float* __restrict__ A, const float* __restrict__ B,
                            float* __restrict__ C, int Ncols, int K_ld, int klen,
                            int gx, int gy, int nsplit,
                            int ltid, int wg, int grp, int ngrp, float* gsm)
{
    float* As = gsm;                 // 2 * 1280
    float* Bs = gsm + 2560;          // 2 * 1280
    const int tx = ltid & 15, ty = ltid >> 4;
    const int isB  = ltid >> 7;
    const int lrow = (ltid & 127) >> 1;
    const int lh   = ltid & 1;
    const int njobs = gx * gy * nsplit;
    const int nch = klen >> 4;

    for (int job = grp; job < njobs; job += ngrp) {
        const int z = job / (gx * gy);
        const int rem = job % (gx * gy);
        const int by = rem / gx, bx = rem % gx;
        const int m0 = by * 64, n0 = bx * 64, kstart = z * klen;

        const float* src0 = isB ? (B + (size_t)(n0 + lrow) * K_ld + kstart + lh * 8)
                                : (A + (size_t)(m0 + lrow) * K_ld + kstart + lh * 8);
        const unsigned dst0 = isB ? su32(&Bs[lrow * RS + lh * 8])
                                  : su32(&As[lrow * RS + lh * 8]);

        float acc[4][4];
#pragma unroll
        for (int i = 0; i < 4; i++)
#pragma unroll
            for (int j = 0; j < 4; j++) acc[i][j] = 0.f;

        wgsync(wg);
        cpa16(dst0, src0);
        cpa16(dst0 + 16, src0 + 4);
        cpcommit();

        for (int c = 0; c < nch; c++) {
            const int cb = c & 1;
            cpwait0();
            wgsync(wg);
            if (c + 1 < nch) {
                const unsigned d = dst0 + (cb ^ 1) * 5120;
                const float* s = src0 + (c + 1) * 16;
                cpa16(d, s);
                cpa16(d + 16, s + 4);
                cpcommit();
            }
            const float* Ab = As + cb * 1280;
            const float* Bb = Bs + cb * 1280;
#pragma unroll
            for (int q = 0; q < 4; q++) {
                float4 af[4], bf[4];
#pragma unroll
                for (int i = 0; i < 4; i++)
                    af[i] = *(const float4*)&Ab[(ty + 16 * i) * RS + q * 4];
#pragma unroll
                for (int j = 0; j < 4; j++)
                    bf[j] = *(const float4*)&Bb[(tx + 16 * j) * RS + q * 4];
#pragma unroll
                for (int i = 0; i < 4; i++)
#pragma unroll
                    for (int j = 0; j < 4; j++) {
                        acc[i][j] += af[i].x * bf[j].x;
                        acc[i][j] += af[i].y * bf[j].y;
                        acc[i][j] += af[i].z * bf[j].z;
                        acc[i][j] += af[i].w * bf[j].w;
                    }
            }
        }

        float* outp = C + (size_t)z * NNODES * Ncols;
#pragma unroll
        for (int i = 0; i < 4; i++)
#pragma unroll
            for (int j = 0; j < 4; j++)
                outp[(size_t)(m0 + ty + 16 * i) * Ncols + n0 + tx + 16 * j] = acc[i][j];
    }
}

// ----------------------------------------------------------------------------
// fc1 GEMM with softmax folded into the A-tile build:
//   A[m,k] = exp(h2[m,k] - mxc[k]) * invc[k];  B = fc1_w  (cp.async)
// Fixed dims: M=512, Ncols=KCC, K=IND, klen=48 (3 chunks), gx=3, gy=8, nsplit=16.
// ----------------------------------------------------------------------------
__device__ void ph_gemm_fc1(const float* __restrict__ h2m, const float* __restrict__ mxc,
                            const float* __restrict__ invc, const float* __restrict__ Bw,
                            float* __restrict__ C,
                            int ltid, int wg, int grp, int ngrp, float* gsm)
{
    float* As = gsm;
    float* Bs = gsm + 2560;
    const int tx = ltid & 15, ty = ltid >> 4;
    const int row = ltid >> 2, kq = (ltid & 3) * 4;
    const int njobs = 3 * 8 * 16;   // 384
    const int nch = 3;

    for (int job = grp; job < njobs; job += ngrp) {
        const int z = job / 24;
        const int rem = job % 24;
        const int by = rem / 3, bx = rem % 3;
        const int m0 = by * 64, n0 = bx * 64, kstart = z * 48;

        const unsigned dstB = su32(&Bs[row * RS + kq]);
        const float* srcB = Bw + (size_t)(n0 + row) * IND + kstart + kq;
        const float* srcA = h2m + (size_t)(m0 + row) * IND + kstart + kq;

        float acc[4][4];
#pragma unroll
        for (int i = 0; i < 4; i++)
#pragma unroll
            for (int j = 0; j < 4; j++) acc[i][j] = 0.f;

        wgsync(wg);
        cpa16(dstB, srcB);
        cpcommit();
        {   // build A chunk 0
            float4 raw = *(const float4*)srcA;
            float4 mx  = *(const float4*)&mxc[kstart + kq];
            float4 iv  = *(const float4*)&invc[kstart + kq];
            float4 v;
            v.x = __expf(raw.x - mx.x) * iv.x;
            v.y = __expf(raw.y - mx.y) * iv.y;
            v.z = __expf(raw.z - mx.z) * iv.z;
            v.w = __expf(raw.w - mx.w) * iv.w;
            *(float4*)&As[row * RS + kq] = v;
        }

        for (int c = 0; c < nch; c++) {
            const int cb = c & 1;
            cpwait0();
            wgsync(wg);
            float4 raw;
            const bool pre = (c + 1 < nch);
            if (pre) {
                cpa16(dstB + (cb ^ 1) * 5120u, srcB + (c + 1) * 16);
                cpcommit();
                raw = *(const float4*)(srcA + (c + 1) * 16);   // LDG early
            }
            const float* Ab = As + cb * 1280;
            const float* Bb = Bs + cb * 1280;
#pragma unroll
            for (int q = 0; q < 4; q++) {
                float4 af[4], bf[4];
#pragma unroll
                for (int i = 0; i < 4; i++)
                    af[i] = *(const float4*)&Ab[(ty + 16 * i) * RS + q * 4];
#pragma unroll
                for (int j = 0; j < 4; j++)
                    bf[j] = *(const float4*)&Bb[(tx + 16 * j) * RS + q * 4];
#pragma unroll
                for (int i = 0; i < 4; i++)
#pragma unroll
                    for (int j = 0; j < 4; j++) {
                        acc[i][j] += af[i].x * bf[j].x;
                        acc[i][j] += af[i].y * bf[j].y;
                        acc[i][j] += af[i].z * bf[j].z;
                        acc[i][j] += af[i].w * bf[j].w;
                    }
            }
            if (pre) {
                const int kg = kstart + (c + 1) * 16 + kq;
                float4 mx = *(const float4*)&mxc[kg];
                float4 iv = *(const float4*)&invc[kg];
                float4 v;
                v.x = __expf(raw.x - mx.x) * iv.x;
                v.y = __expf(raw.y - mx.y) * iv.y;
                v.z = __expf(raw.z - mx.z) * iv.z;
                v.w = __expf(raw.w - mx.w) * iv.w;
                *(float4*)&As[(cb ^ 1) * 1280 + row * RS + kq] = v;
            }
        }

        float* outp = C + (size_t)z * NNODES * KCC;
#pragma unroll
        for (int i = 0; i < 4; i++)
#pragma unroll
            for (int j = 0; j < 4; j++)
                outp[(size_t)(m0 + ty + 16 * i) * KCC + n0 + tx + 16 * j] = acc[i][j];
    }
}

// ----------------------------------------------------------------------------
// Pipelined aggregation GEMM, chunk=16, one barrier per chunk.
// ----------------------------------------------------------------------------
__device__ void ph_gemm_agg(const float* __restrict__ Z, float* __restrict__ C,
                            const float* __restrict__ ssrc, const float* __restrict__ sdst,
                            const float* __restrict__ Af, const float* __restrict__ Cf,
                            const float* __restrict__ Bp, const float* __restrict__ Dp,
                            int ldz, int hd, int gx, int gy, int nsplit, int H,
                            int klen, int ldc,
                            int ltid, int wg, int grp, int ngrp, float* gsm)
{
    float* Asb = gsm;              // 2 * 1088
    float* Zs  = gsm + 2176;       // 2 * 1088
    float* Ex  = gsm + 4352;       // 192
    const int tx = ltid & 15, ty = ltid >> 4;
    const int zrow = ltid >> 4, zf4 = ltid & 15;
    const int ail = ltid >> 4, aj4 = (ltid & 15) * 4;
    const int jobs_per_h = gx * gy * nsplit;
    const int njobs = H * jobs_per_h;
    const int nch = klen >> 4;

    for (int job = grp; job < njobs; job += ngrp) {
        const int h = job / jobs_per_h;
        int rem = job % jobs_per_h;
        const int z = rem / (gx * gy); rem %= gx * gy;
        const int by = rem / gx, bx = rem % gx;
        const int m0 = by * 64, ncol0 = h * hd + bx * 64, kstart = z * klen;
        const float* ss = ssrc + h * NNODES;
        const float* af = Af + h * NNODES;
        const float* cf = Cf + h * NNODES;

        auto build = [&](int cc, float* dst) {
            int ig = kstart + cc * 16 + ail;
            float ssv = ss[ig], afv = af[ig], cfv = cf[ig];
            float* exd = Ex; float* exb = Ex + 64; float* exD = Ex + 128;
            int jj = aj4;
            float4 w;
            float x0 = ssv + exd[jj + 0];
            float x1 = ssv + exd[jj + 1];
            float x2 = ssv + exd[jj + 2];
            float x3 = ssv + exd[jj + 3];
            w.x = x0 > 0.f ? afv * exb[jj + 0] : cfv * exD[jj + 0];
            w.y = x1 > 0.f ? afv * exb[jj + 1] : cfv * exD[jj + 1];
            w.z = x2 > 0.f ? afv * exb[jj + 2] : cfv * exD[jj + 2];
            w.w = x3 > 0.f ? afv * exb[jj + 3] : cfv * exD[jj + 3];
            if (ig == m0 + jj + 0) w.x = 0.f;
            if (ig == m0 + jj + 1) w.y = 0.f;
            if (ig == m0 + jj + 2) w.z = 0.f;
            if (ig == m0 + jj + 3) w.w = 0.f;
            *(float4*)&dst[ail * 68 + aj4] = w;
        };

        wgsync(wg);
        if (ltid < 64) {
            int j = m0 + ltid;
            Ex[ltid]       = sdst[h * NNODES + j];
            Ex[64 + ltid]  = Bp[h * NNODES + j];
            Ex[128 + ltid] = Dp[h * NNODES + j];
        }
        wgsync(wg);                         // Ex visible to ALL threads

        build(0, Asb);
        const float* srcZ = Z + (size_t)(kstart + zrow) * ldz + ncol0 + zf4 * 4;
        const unsigned dstZ = su32(&Zs[zrow * 68 + zf4 * 4]);
        cpa16(dstZ, srcZ);
        cpcommit();

        float acc[4][4];
#pragma unroll
        for (int i = 0; i < 4; i++)
#pragma unroll
            for (int j = 0; j < 4; j++) acc[i][j] = 0.f;

        for (int c = 0; c < nch; c++) {
            const int cb = c & 1;
            cpwait0();
            wgsync(wg);
            if (c + 1 < nch) {
                cpa16(dstZ + (cb ^ 1) * 4352, srcZ + (size_t)(c + 1) * 16 * ldz);
                cpcommit();
                build(c + 1, Asb + (cb ^ 1) * 1088);
            }
            const float* Ab = Asb + cb * 1088;
            const float* Zb = Zs  + cb * 1088;
#pragma unroll
            for (int kk = 0; kk < 16; kk++) {
                float4 a = *(const float4*)&Ab[kk * 68 + ty * 4];
                float4 b = *(const float4*)&Zb[kk * 68 + tx * 4];
                float a4[4] = {a.x, a.y, a.z, a.w};
                float b4[4] = {b.x, b.y, b.z, b.w};
#pragma unroll
                for (int i = 0; i < 4; i++)
#pragma unroll
                    for (int j = 0; j < 4; j++) acc[i][j] += a4[i] * b4[j];
            }
        }

        float* outp = C + (size_t)z * NNODES * ldc;
#pragma unroll
        for (int i = 0; i < 4; i++)
#pragma unroll
            for (int j = 0; j < 4; j++)
                outp[(size_t)(m0 + ty * 4 + i) * ldc + ncol0 + tx * 4 + j] = acc[i][j];
    }
}

// ----------------------------------------------------------------------------
// Combine k-split partials
// ----------------------------------------------------------------------------
__device__ void ph_combine(float* __restrict__ out, const float* __restrict__ part,
                           int nparts, int total, int ncols,
                           const float* __restrict__ bias, int act)
{
    for (int idx = blockIdx.x * NT + threadIdx.x; idx < total; idx += gridDim.x * NT) {
        float s = 0.f;
        for (int p = 0; p < nparts; p++) s += part[(size_t)p * total + idx];
        if (bias) s += bias[idx % ncols];
        if (act == 1) s = fmaxf(s, 0.f);
        else if (act == 2) s = s > 0.f ? s : expm1f(s);
        out[idx] = s;
    }
}

// ----------------------------------------------------------------------------
// Attention scores
// ----------------------------------------------------------------------------
__device__ void ph_scores(const float* __restrict__ z, int ldz,
                          const float* __restrict__ a, int D,
                          float* __restrict__ ssrc, float* __restrict__ sdst, int H)
{
    const int lane = threadIdx.x & 31;
    const int gw = blockIdx.x * (NT / 32) + (threadIdx.x >> 5);
    const int nw = gridDim.x * (NT / 32);
    for (int w = gw; w < H * NNODES; w += nw) {
        int h = w / NNODES, i = w % NNODES;
        const float* zr = z + (size_t)i * ldz + h * D;
        const float* ar = a + (size_t)h * 2 * D;
        float s1 = 0.f, s2 = 0.f;
        for (int d = lane; d < D; d += 32) {
            float v = zr[d];
            s1 += v * ar[d];
            s2 += v * ar[D + d];
        }
#pragma unroll
        for (int o = 16; o; o >>= 1) {
            s1 += __shfl_xor_sync(0xffffffffu, s1, o);
            s2 += __shfl_xor_sync(0xffffffffu, s2, o);
        }
        if (lane == 0) { ssrc[h * NNODES + i] = s1; sdst[h * NNODES + i] = s2; }
    }
}

// ----------------------------------------------------------------------------
// Separable-softmax stats
// ----------------------------------------------------------------------------
__device__ void ph_stats(const float* __restrict__ ssrc, const float* __restrict__ sdst,
                         float* __restrict__ Af, float* __restrict__ Cf,
                         float* __restrict__ Bpg, float* __restrict__ Dpg,
                         int H, int ltid, int wg, int grp, int ngrp, float* gsm)
{
    float* ss  = gsm;
    float* aa  = gsm + 512;
    float* cc  = gsm + 1024;
    float* rm1 = gsm + 1536;
    float* rm2 = gsm + 1792;
    int*   ri1 = (int*)(gsm + 2048);
    const int cpj = NNODES / 64;
    const int njobs = H * cpj;

    for (int job = grp; job < njobs; job += ngrp) {
        const int h = job / cpj, jc = job % cpj;
        wgsync(wg);
        for (int i = ltid; i < NNODES; i += GSZ) ss[i] = ssrc[h * NNODES + i];
        wgsync(wg);

        float m1 = -1e30f, m2 = -1e30f; int i1 = -1;
        for (int i = ltid; i < NNODES; i += GSZ) {
            float v = ss[i];
            if (v > m1) { m2 = m1; m1 = v; i1 = i; }
            else if (v > m2) m2 = v;
        }
        rm1[ltid] = m1; rm2[ltid] = m2; ri1[ltid] = i1;
        wgsync(wg);
        if (ltid < 32) {
            float a1 = rm1[ltid], a2 = rm2[ltid]; int ai = ri1[ltid];
            for (int t = ltid + 32; t < GSZ; t += 32) {
                float b1 = rm1[t], b2 = rm2[t];
                if (b1 > a1) { a2 = fmaxf(a1, b2); a1 = b1; ai = ri1[t]; }
                else         { a2 = fmaxf(a2, b1); }
            }
            rm1[ltid] = a1; rm2[ltid] = a2; ri1[ltid] = ai;
        }
        wgsync(wg);
        if (ltid == 0) {
            float a1 = rm1[0], a2 = rm2[0]; int ai = ri1[0];
            for (int t = 1; t < 32; t++) {
                float b1 = rm1[t], b2 = rm2[t];
                if (b1 > a1) { a2 = fmaxf(a1, b2); a1 = b1; ai = ri1[t]; }
                else         { a2 = fmaxf(a2, b1); }
            }
            rm1[0] = a1; rm2[0] = a2; ri1[0] = ai;
        }
        wgsync(wg);
        const float Ms = rm1[0], M2 = rm2[0];
        const int iarg = ri1[0];

        for (int i = ltid; i < NNODES; i += GSZ) {
            float d = ss[i] - Ms;
            aa[i] = __expf(d);
            cc[i] = __expf(0.01f * d);
        }
        wgsync(wg);
        if (jc == 0) {
            for (int i = ltid; i < NNODES; i += GSZ) {
                Af[h * NNODES + i] = aa[i];
                Cf[h * NNODES + i] = cc[i];
            }
        }

        const int wid = ltid >> 5, lane = ltid & 31;
        for (int jj = wid; jj < 64; jj += 8) {
            int j = jc * 64 + jj;
            float sd = sdst[h * NNODES + j];
            float smx = (j == iarg) ? M2 : Ms;
            float t0 = smx + sd;
            float mxj = t0 > 0.f ? t0 : 0.01f * t0;
            float Bj = __expf(Ms + sd - mxj);
            float Dj = __expf(0.01f * (Ms + sd) - mxj);
            float ssum = 0.f;
            for (int i = lane; i < NNODES; i += 32) {
                if (i == j) continue;
                float x = ss[i] + sd;
                ssum += (x > 0.f) ? aa[i] * Bj : cc[i] * Dj;
            }
#pragma unroll
            for (int o = 16; o; o >>= 1) ssum += __shfl_xor_sync(0xffffffffu, ssum, o);
            if (lane == 0) {
                float inv = 1.f / ssum;
                Bpg[h * NNODES + j] = Bj * inv;
                Dpg[h * NNODES + j] = Dj * inv;
            }
        }
    }
}

// ----------------------------------------------------------------------------
// Column softmax stats
// ----------------------------------------------------------------------------
__device__ void ph_colstats(const float* __restrict__ h2,
                            float* __restrict__ mxc, float* __restrict__ invc,
                            int ltid, int wg, int grp, int ngrp, float* gsm)
{
    float* red  = gsm;
    float* red2 = gsm + 256;
    const int fl = ltid & 63, rg = ltid >> 6;
    for (int job = grp; job < IND / 64; job += ngrp) {
        const int f = job * 64 + fl;
        wgsync(wg);
        float m = -1e30f;
        for (int r0 = rg; r0 < NNODES; r0 += 4) m = fmaxf(m, h2[(size_t)r0 * IND + f]);
        red[rg * 64 + fl] = m;
        wgsync(wg);
        if (rg == 0)
            red[fl] = fmaxf(fmaxf(red[fl], red[64 + fl]), fmaxf(red[128 + fl], red[192 + fl]));
        wgsync(wg);
        const float mf = red[fl];
        float s = 0.f;
        for (int r0 = rg; r0 < NNODES; r0 += 4) s += __expf(h2[(size_t)r0 * IND + f] - mf);
        red2[rg * 64 + fl] = s;
        wgsync(wg);
        if (rg == 0) {
            float t = red2[fl] + red2[64 + fl] + red2[128 + fl] + red2[192 + fl];
            mxc[f] = mf;
            invc[f] = 1.f / t;
        }
    }
}

// ----------------------------------------------------------------------------
// Column sum + fc2
// ----------------------------------------------------------------------------
__device__ void ph_colsum(const float* __restrict__ r, float* __restrict__ rsum,
                          int ltid, int wg, int grp, int ngrp, float* gsm)
{
    const int cl = ltid & 31, rg = ltid >> 5;
    for (int job = grp; job < KCC / 32; job += ngrp) {
        const int c = job * 32 + cl;
        wgsync(wg);
        float s = 0.f;
        for (int r0 = rg; r0 < NNODES; r0 += 8) s += r[(size_t)r0 * KCC + c];
        gsm[rg * 32 + cl] = s;
        wgsync(wg);
        if (rg == 0) {
            float t = 0.f;
            for (int g = 0; g < 8; g++) t += gsm[g * 32 + cl];
            rsum[c] = t;
        }
    }
}

__device__ void ph_fc2(const float* __restrict__ rsum, const float* __restrict__ w,
                       const float* __restrict__ b, float* __restrict__ out)
{
    const int lane = threadIdx.x & 31;
    const int gw = blockIdx.x * (NT / 32) + (threadIdx.x >> 5);
    const int nw = gridDim.x * (NT / 32);
    for (int o = gw; o < OUTDIM; o += nw) {
        float s = 0.f;
        for (int k = lane; k < KCC; k += 32) s += rsum[k] * w[(size_t)o * KCC + k];
#pragma unroll
        for (int of = 16; of; of >>= 1) s += __shfl_xor_sync(0xffffffffu, s, of);
        if (lane == 0) out[o] = (float)NNODES * b[o] + s;
    }
}

// ----------------------------------------------------------------------------
// Persistent mega-kernel
// ----------------------------------------------------------------------------
__global__ void __launch_bounds__(NT, 1)
gat_mega(const float* __restrict__ X,  const float* __restrict__ W1,
         const float* __restrict__ a1, const float* __restrict__ W2,
         const float* __restrict__ a2, const float* __restrict__ fc1w,
         const float* __restrict__ fc1b, const float* __restrict__ fc2w,
         const float* __restrict__ fc2b, float* __restrict__ out)
{
    extern __shared__ float sm[];
    const int wg = threadIdx.x >> 8;
    const int ltid = threadIdx.x & 255;
    float* gsm = sm + wg * SMG;
    const int grp = wg * gridDim.x + blockIdx.x;   // spread jobs across SMs
    const int ngrp = gridDim.x * NG;

    // P0: z1 partials = X @ W1^T, K=768 split 12 (384 jobs)
    ph_gemm_abt(X, W1, g_part, HD1, IND, 64, HD1 / 64, NNODES / 64, 12,
                ltid, wg, grp, ngrp, gsm);
    gridbar();
    // P1: combine -> z1
    ph_combine(g_z1, g_part, 12, NNODES * HD1, HD1, nullptr, 0);
    gridbar();
    // P2: layer1 scores
    ph_scores(g_z1, HD1, a1, HIDD, g_ssrc, g_sdst, NHEAD);
    gridbar();
    // P3: layer1 stats
    ph_stats(g_ssrc, g_sdst, g_Af, g_Cf, g_Bp, g_Dp, NHEAD, ltid, wg, grp, ngrp, gsm);
    gridbar();
    // P4: agg1 partials, split 8 (256 jobs)
    ph_gemm_agg(g_z1, g_part, g_ssrc, g_sdst, g_Af, g_Cf, g_Bp, g_Dp,
                HD1, HIDD, 1, NNODES / 64, 8, NHEAD, 64, HD1,
                ltid, wg, grp, ngrp, gsm);
    gridbar();
    // P5: combine + ELU -> h1
    ph_combine(g_h1, g_part, 8, NNODES * HD1, HD1, nullptr, 2);
    gridbar();
    // P6: z2 partials = h1 @ W2^T, K=256 split 4 (384 jobs)
    ph_gemm_abt(g_h1, W2, g_part, IND, HD1, 64, IND / 64, NNODES / 64, 4,
                ltid, wg, grp, ngrp, gsm);
    gridbar();
    // P6b: combine -> z2
    ph_combine(g_z2, g_part, 4, NNODES * IND, IND, nullptr, 0);
    gridbar();
    // P7: layer2 scores
    ph_scores(g_z2, IND, a2, IND, g_ssrc, g_sdst, 1);
    gridbar();
    // P8: layer2 stats
    ph_stats(g_ssrc, g_sdst, g_Af, g_Cf, g_Bp, g_Dp, 1, ltid, wg, grp, ngrp, gsm);
    gridbar();
    // P9: agg2 partials, split 4 (384 jobs)
    ph_gemm_agg(g_z2, g_part, g_ssrc, g_sdst, g_Af, g_Cf, g_Bp, g_Dp,
                IND, 0, IND / 64, NNODES / 64, 4, 1, 128, IND,
                ltid, wg, grp, ngrp, gsm);
    gridbar();
    // P10: combine -> h2
    ph_combine(g_h2, g_part, 4, NNODES * IND, IND, nullptr, 0);
    gridbar();
    // P11: column softmax stats
    ph_colstats(g_h2, g_mxc, g_invc, ltid, wg, grp, ngrp, gsm);
    gridbar();
    // P12: fc1 partials = softmax(h2) @ fc1_w^T (exp fused), split 16 (384 jobs)
    ph_gemm_fc1(g_h2, g_mxc, g_invc, fc1w, g_part, ltid, wg, grp, ngrp, gsm);
    gridbar();
    // P13: combine + bias + relu -> r
    ph_combine(g_r, g_part, 16, NNODES * KCC, KCC, fc1b, 1);
    gridbar();
    // P14: column sum -> rsum
    ph_colsum(g_r, g_rsum, ltid, wg, grp, ngrp, gsm);
    gridbar();
    // P15: fc2 -> out
    ph_fc2(g_rsum, fc2w, fc2b, out);
}

// ----------------------------------------------------------------------------
// Launch
// ----------------------------------------------------------------------------
extern "C" void kernel_launch(void* const* d_in, const int* in_sizes, int n_in,
                              void* d_out, int out_size)
{
    const float* X     = (const float*)d_in[0];
    const float* W1    = (const float*)d_in[1];
    const float* a1    = (const float*)d_in[2];
    const float* W2    = (const float*)d_in[3];
    const float* a2    = (const float*)d_in[4];
    const float* fc1_w = (const float*)d_in[5];
    const float* fc1_b = (const float*)d_in[6];
    const float* fc2_w = (const float*)d_in[7];
    const float* fc2_b = (const float*)d_in[8];

    int sms = 148;
    cudaDeviceGetAttribute(&sms, cudaDevAttrMultiProcessorCount, 0);

    const size_t smbytes = (size_t)NG * SMG * sizeof(float);   // 60 KB
    cudaFuncSetAttribute(gat_mega, cudaFuncAttributeMaxDynamicSharedMemorySize,
                         (int)smbytes);

    gat_mega<<<sms, NT, smbytes>>>(X, W1, a1, W2, a2, fc1_w, fc1_b, fc2_w, fc2_b,
                                   (float*)d_out);
}